// round 14
// baseline (speedup 1.0000x reference)
#include <cuda_runtime.h>
#include <cuda_bf16.h>
#include <cstdint>

#define Bq   32
#define Sq   96
#define TD   63
#define Tq   64
#define Eq   256
#define HEq  512
#define Gq   2048
#define EDq  1024
#define VTq  16000
#define PKq  1536
#define BH   16384
#define XGS  6291456   // B*S*G

__device__ __align__(16) float g_emb [Bq*Sq*Eq];
__device__ __align__(16) float g_xg  [2*XGS];
__device__ __align__(16) float g_xgT [2*XGS];
__device__ __align__(16) float g_x1  [Bq*Sq*EDq];
__device__ __align__(16) float g_enc [Bq*Sq*EDq];
__device__ __align__(16) float g_encA[Bq*Sq*HEq];
__device__ __align__(16) float g_aWT [HEq*EDq];
__device__ __align__(16) float g_bzero[512];        // stays zero (never written)
__device__ __align__(16) float g_eh  [8*BH];
__device__ __align__(16) float g_ec  [8*BH];
__device__ __align__(16) float g_dh  [4*BH];
__device__ __align__(16) float g_dc  [4*BH];
__device__ __align__(16) float g_embd[TD*Bq*Eq];
__device__ __align__(16) float g_eg  [TD*Bq*Gq];
__device__ __align__(16) float g_egT [TD*Bq*Gq];
__device__ __align__(16) float g_feat[TD*Bq*PKq];
__device__ __align__(16) float g_dh3 [HEq*Bq];
__device__ __align__(16) unsigned g_hx [2*4*2*8192];
__device__ __align__(16) unsigned g_cx [2*16384];
__device__ __align__(16) unsigned g_wf [9437184];

__device__ unsigned g_cnt[4];
__device__ unsigned g_gen[4];
__device__ __align__(128) unsigned g_cnt8[8*32];   // 8 counters, 128B apart
__device__ unsigned g_gen8;

__device__ __forceinline__ float sigf(float x){ return 1.f/(1.f + __expf(-x)); }
__device__ __forceinline__ float wsum(float v){
#pragma unroll
    for (int o=16;o;o>>=1) v += __shfl_xor_sync(0xffffffffu,v,o);
    return v;
}
__device__ __forceinline__ float wmax(float v){
#pragma unroll
    for (int o=16;o;o>>=1) v = fmaxf(v,__shfl_xor_sync(0xffffffffu,v,o));
    return v;
}

__device__ __forceinline__ unsigned atom_add_acqrel(unsigned* p, unsigned v){
    unsigned o;
    asm volatile("atom.acq_rel.gpu.global.add.u32 %0,[%1],%2;"
                 : "=r"(o) : "l"(p), "r"(v) : "memory");
    return o;
}
__device__ __forceinline__ unsigned ld_acq(const unsigned* p){
    unsigned v;
    asm volatile("ld.acquire.gpu.global.u32 %0,[%1];" : "=r"(v) : "l"(p) : "memory");
    return v;
}

// legacy single-counter barrier (encoder)
__device__ __forceinline__ void gbar(int id, unsigned nb, unsigned base, unsigned idx){
    __syncthreads();
    if (threadIdx.x == 0){
        if (atom_add_acqrel(&g_cnt[id], 1u) == nb-1u){
            atomicExch(&g_cnt[id], 0u);
            atom_add_acqrel(&g_gen[id], 1u);
        } else {
            while (ld_acq(&g_gen[id]) - base < idx) { }
        }
    }
    __syncthreads();
}

// reset decoder barrier state before every dec_all launch (stream-ordered)
__global__ void k_rst(){
    if (threadIdx.x < 8) g_cnt8[threadIdx.x*32] = 0u;
    if (threadIdx.x == 0) g_gen8 = 0u;
}

// decoder barrier: spread arrivals over 8 padded counters; block DNB-1 releases.
// counters zeroed by k_rst each launch -> absolute thresholds, no baseline race.
#define DNB 128u
__device__ __forceinline__ void dbar(int bk, unsigned idx){
    __syncthreads();
    if (threadIdx.x == 0){
        atom_add_acqrel(&g_cnt8[(bk&7)*32], 1u);
        if (bk == (int)DNB-1){
            for(;;){
                unsigned s=0;
#pragma unroll
                for (int j=0;j<8;j++) s += ld_acq(&g_cnt8[j*32]);
                if (s >= DNB*idx) break;
            }
            atom_add_acqrel(&g_gen8, 1u);
        }
        while (ld_acq(&g_gen8) < idx) { }
    }
    __syncthreads();
}

__global__ void k_zero(float* a, float* b, int n){
    int i = blockIdx.x*256 + threadIdx.x;
    if (i < n){ a[i]=0.f; b[i]=0.f; }
}

__global__ void k_embed_src(const int* __restrict__ src, const float* __restrict__ emb,
                            float* __restrict__ o){
    int idx = blockIdx.x*256 + threadIdx.x;
    o[idx] = emb[(size_t)src[idx>>8]*Eq + (idx&255)];
}

__global__ void k_embed_tgt(const int* __restrict__ tgt, const float* __restrict__ emb,
                            float* __restrict__ o){
    int idx = blockIdx.x*256 + threadIdx.x;
    int m = idx>>8, t = m>>5, b = m&31;
    o[idx] = emb[(size_t)tgt[b*Tq+t]*Eq + (idx&255)];
}

__global__ __launch_bounds__(256) void k_xT(const float* __restrict__ xg,
                                            float* __restrict__ xgT){
    __shared__ float tl[32][33];
    int bid = blockIdx.x;
    int ng = bid & 63, s = (bid>>6)%Sq, dir = bid/(Sq*64);
    int n0 = ng*32;
    int nn = threadIdx.x & 31, bq = threadIdx.x >> 5;
    for (int b = bq; b < 32; b += 8)
        tl[nn][b] = xg[(size_t)dir*XGS + ((size_t)b*Sq + s)*Gq + n0 + nn];
    __syncthreads();
    int b2 = threadIdx.x & 31, n2 = threadIdx.x >> 5;
    for (int n = n2; n < 32; n += 8)
        xgT[(((size_t)dir*Sq + s)*Gq + n0 + n)*32 + b2] = tl[n][b2];
}

// eg[(t*32+b)*G + n] -> egT[(t*G + n)*32 + b]
__global__ __launch_bounds__(256) void k_egT(const float* __restrict__ eg,
                                             float* __restrict__ egT){
    __shared__ float tl[32][33];
    int bid = blockIdx.x;               // t*64 + ng
    int ng = bid & 63, t = bid >> 6;
    int n0 = ng*32;
    int nn = threadIdx.x & 31, bq = threadIdx.x >> 5;
    for (int b = bq; b < 32; b += 8)
        tl[nn][b] = eg[((size_t)t*32 + b)*Gq + n0 + nn];
    __syncthreads();
    int b2 = threadIdx.x & 31, n2 = threadIdx.x >> 5;
    for (int n = n2; n < 32; n += 8)
        egT[((size_t)t*Gq + n0 + n)*32 + b2] = tl[n][b2];
}

// attn_W [1024][512] -> aWT [512][1024]
__global__ __launch_bounds__(256) void k_aT(const float* __restrict__ A,
                                            float* __restrict__ AT){
    __shared__ float tl[32][33];
    int k0 = blockIdx.x*32, e0 = blockIdx.y*32;
    int li = threadIdx.x&31, wi = threadIdx.x>>5;
    for (int r=wi;r<32;r+=8) tl[r][li] = A[(size_t)(e0+r)*HEq + k0+li];
    __syncthreads();
    for (int r=wi;r<32;r+=8) AT[(size_t)(k0+r)*EDq + e0+li] = tl[li][r];
}

// ===== decoder weight fragment precompute =====
__global__ __launch_bounds__(256) void k_wf(
    const float* __restrict__ dWih0, const float* __restrict__ dWhh0,
    const float* __restrict__ dWih,  const float* __restrict__ dWhh,
    unsigned* __restrict__ wf)
{
    int wid = blockIdx.x*8 + (threadIdx.x>>5);
    int lane = threadIdx.x & 31;
    int l, bk, ks, KS; size_t base;
    if (wid < 128*96){ l=0; bk=wid/96; ks=wid%96; KS=96; base=0; }
    else {
        int w2 = wid - 128*96;
        l = 1 + w2/(128*64);
        int rem = w2 % (128*64);
        bk = rem/64; ks = rem%64; KS=64;
        base = 3145728 + (size_t)(l-1)*2097152;
    }
    const float* W; int ld, col0;
    if (l==0){
        if (ks<64){ W=dWih0; ld=1280; col0=256+ks*16; }
        else      { W=dWhh0; ld=512;  col0=(ks-64)*16; }
    } else {
        if (ks<32){ W=dWih + (size_t)(l-1)*Gq*HEq; ld=512; col0=ks*16; }
        else      { W=dWhh + (size_t)(l-1)*Gq*HEq; ld=512; col0=(ks-32)*16; }
    }
    int rl = lane>>2, c2 = (lane&3)*2;
    unsigned* outp = wf + base + (size_t)(bk*KS+ks)*256 + lane*4;
#pragma unroll
    for (int q=0;q<4;q++){
        int rloc = rl + ((q&1)?8:0);
        int col  = col0 + c2 + ((q&2)?8:0);
        int h = bk*4 + (rloc>>2), g = rloc&3;
        const float* wr = W + (size_t)(g*HEq + h)*ld + col;
        float f0 = wr[0], f1 = wr[1];
        __nv_bfloat16 h0=__float2bfloat16_rn(f0), h1=__float2bfloat16_rn(f1);
        float r0 = f0-__bfloat162float(h0), r1 = f1-__bfloat162float(h1);
        unsigned hi = (unsigned)__bfloat16_as_ushort(h0) | ((unsigned)__bfloat16_as_ushort(h1)<<16);
        unsigned lo = (unsigned)__bfloat16_as_ushort(__float2bfloat16_rn(r0))
                    | ((unsigned)__bfloat16_as_ushort(__float2bfloat16_rn(r1))<<16);
        outp[q] = hi;
        outp[128+q] = lo;
    }
}

// ===== split-bf16 tensor-core GEMM (R9 proven version) =====
__device__ __forceinline__ uint32_t smaddr(const void* p){
    return (uint32_t)__cvta_generic_to_shared(p);
}
__device__ __forceinline__ void ldsm4(uint32_t* r, uint32_t a){
    asm volatile("ldmatrix.sync.aligned.m8n8.x4.shared.b16 {%0,%1,%2,%3},[%4];\n"
        : "=r"(r[0]),"=r"(r[1]),"=r"(r[2]),"=r"(r[3]) : "r"(a));
}
__device__ __forceinline__ void mma16816(float* d, const uint32_t* a, const uint32_t* b){
    asm volatile("mma.sync.aligned.m16n8k16.row.col.f32.bf16.bf16.f32 "
        "{%0,%1,%2,%3},{%4,%5,%6,%7},{%8,%9},{%0,%1,%2,%3};\n"
        : "+f"(d[0]),"+f"(d[1]),"+f"(d[2]),"+f"(d[3])
        : "r"(a[0]),"r"(a[1]),"r"(a[2]),"r"(a[3]),"r"(b[0]),"r"(b[1]));
}
#define SROW 40

__device__ __forceinline__ void cvt16(const float* f, unsigned short* hD, unsigned short* lD){
    uint32_t h[8], l[8];
#pragma unroll
    for (int j=0;j<8;j++){
        float f0=f[2*j], f1=f[2*j+1];
        __nv_bfloat16 h0=__float2bfloat16_rn(f0), h1=__float2bfloat16_rn(f1);
        float l0=f0-__bfloat162float(h0), l1=f1-__bfloat162float(h1);
        __nv_bfloat16 g0=__float2bfloat16_rn(l0), g1=__float2bfloat16_rn(l1);
        h[j] = (uint32_t)__bfloat16_as_ushort(h0) | ((uint32_t)__bfloat16_as_ushort(h1)<<16);
        l[j] = (uint32_t)__bfloat16_as_ushort(g0) | ((uint32_t)__bfloat16_as_ushort(g1)<<16);
    }
    ((uint4*)hD)[0] = make_uint4(h[0],h[1],h[2],h[3]);
    ((uint4*)hD)[1] = make_uint4(h[4],h[5],h[6],h[7]);
    ((uint4*)lD)[0] = make_uint4(l[0],l[1],l[2],l[3]);
    ((uint4*)lD)[1] = make_uint4(l[4],l[5],l[6],l[7]);
}

__global__ __launch_bounds__(256,2) void hgemm_split(
    const float* __restrict__ A, int lda,
    const float* __restrict__ Bw, int ldb,
    const float* __restrict__ bias, float* __restrict__ C,
    int M, int N, int K, int permute)
{
    __shared__ __align__(16) unsigned short Ah[128*SROW], Al[128*SROW];
    __shared__ __align__(16) unsigned short Bh[128*SROW], Bl[128*SROW];

    const int bm = blockIdx.y*128, bn = blockIdx.x*128;
    const int tid = threadIdx.x, lane = tid&31, wid = tid>>5;
    const int wm = wid&3, wn = wid>>2;

    float acc[2][8][4];
#pragma unroll
    for (int a_=0;a_<2;a_++)
#pragma unroll
        for (int b_=0;b_<8;b_++)
#pragma unroll
            for (int c_=0;c_<4;c_++) acc[a_][b_][c_]=0.f;

    const int lrow = tid>>1, lhalf = (tid&1)*16;
    int gm = bm + lrow; if (gm >= M) gm = M-1;
    const float* aG = A + (size_t)gm*lda + lhalf;
    const float* bG = Bw + (size_t)(bn+lrow)*ldb + lhalf;
    unsigned short* ahS = Ah + lrow*SROW + lhalf;
    unsigned short* alS = Al + lrow*SROW + lhalf;
    unsigned short* bhS = Bh + lrow*SROW + lhalf;
    unsigned short* blS = Bl + lrow*SROW + lhalf;

    const uint32_t aOff = ((uint32_t)(wm*32 + (lane&15))*SROW + (lane>>4)*8)*2;
    const uint32_t bRow = (uint32_t)(wn*64 + (lane&7) + ((lane&16)?8:0));
    const uint32_t bOff = (bRow*SROW + ((lane&8)?8:0))*2;
    const uint32_t aBh = smaddr(Ah)+aOff, aBl = smaddr(Al)+aOff;
    const uint32_t bBh = smaddr(Bh)+bOff, bBl = smaddr(Bl)+bOff;

    for (int k0=0; k0<K; k0+=32){
        __syncthreads();
        {
            float fb[16];
            const float4* ap = (const float4*)(aG + k0);
            float4 v0=ap[0], v1=ap[1], v2=ap[2], v3=ap[3];
            *(float4*)&fb[0]=v0; *(float4*)&fb[4]=v1; *(float4*)&fb[8]=v2; *(float4*)&fb[12]=v3;
            cvt16(fb, ahS, alS);
            const float4* bp = (const float4*)(bG + k0);
            v0=bp[0]; v1=bp[1]; v2=bp[2]; v3=bp[3];
            *(float4*)&fb[0]=v0; *(float4*)&fb[4]=v1; *(float4*)&fb[8]=v2; *(float4*)&fb[12]=v3;
            cvt16(fb, bhS, blS);
        }
        __syncthreads();
#pragma unroll
        for (int kk=0; kk<32; kk+=16){
            uint32_t ah[2][4], al[2][4];
#pragma unroll
            for (int mt=0; mt<2; mt++){
                ldsm4(ah[mt], aBh + (mt*16*SROW + kk)*2);
                ldsm4(al[mt], aBl + (mt*16*SROW + kk)*2);
            }
#pragma unroll
            for (int ntp=0; ntp<4; ntp++){
                uint32_t bh[4], bl[4];
                ldsm4(bh, bBh + (ntp*16*SROW + kk)*2);
                ldsm4(bl, bBl + (ntp*16*SROW + kk)*2);
#pragma unroll
                for (int mt=0; mt<2; mt++){
                    float* c0 = acc[mt][ntp*2+0];
                    float* c1 = acc[mt][ntp*2+1];
                    mma16816(c0, ah[mt], bh+0);
                    mma16816(c0, ah[mt], bl+0);
                    mma16816(c0, al[mt], bh+0);
                    mma16816(c1, ah[mt], bh+2);
                    mma16816(c1, ah[mt], bl+2);
                    mma16816(c1, al[mt], bh+2);
                }
            }
        }
    }

    const int mr = lane>>2, nc = (lane&3)*2;
#pragma unroll
    for (int mt=0; mt<2; mt++){
#pragma unroll
        for (int nt=0; nt<8; nt++){
            int n = bn + wn*64 + nt*8 + nc;
            float b0 = bias[n], b1 = bias[n+1];
            const float* ac = acc[mt][nt];
#pragma unroll
            for (int rr=0; rr<2; rr++){
                int m = bm + wm*32 + mt*16 + mr + rr*8;
                if (m < M){
                    size_t crow = permute ? (size_t)((m&31)*63 + (m>>5)) : (size_t)m;
                    float* cp = C + crow*(size_t)N + n;
                    cp[0] = ac[rr*2+0] + b0;
                    cp[1] = ac[rr*2+1] + b1;
                }
            }
        }
    }
}

// ---------- persistent encoder layer ----------
__global__ __launch_bounds__(256) void enc_layer(
    const float* __restrict__ xgT, const float* __restrict__ Whh,
    const int* __restrict__ lens,
    float* __restrict__ h, float* __restrict__ c,
    float* __restrict__ outp)
{
    extern __shared__ float sm[];
    float* ws = sm;
    float* xs = sm + 16384;

    const int dir = blockIdx.x >> 6, bb = blockIdx.x & 63;
    const int tid = threadIdx.x, w = tid>>5, lane = tid&31;
    const int h_idx = bb*8 + w;

    const float* wbase = Whh + (size_t)dir*Gq*HEq;
#pragma unroll
    for (int g=0; g<4; g++){
        const float4* srcp = (const float4*)(wbase + (size_t)(g*HEq + h_idx)*HEq);
        float4* dst = (float4*)(ws + (w*4+g)*HEq);
        for (int i=lane; i<128; i+=32) dst[i] = srcp[i];
    }
    __syncthreads();

    unsigned base = 0;
    if (tid == 0) base = ld_acq(&g_gen[dir]);

    const int len = lens[lane];
    float* hD = h + (size_t)dir*2*BH;
    float* cD = c + (size_t)dir*2*BH;
    const float* w0 = ws + (w*4+0)*HEq;
    const float* w1 = ws + (w*4+1)*HEq;
    const float* w2 = ws + (w*4+2)*HEq;
    const float* w3 = ws + (w*4+3)*HEq;

    for (int s=0; s<Sq; s++){
        const int pp = s&1, po = pp^1;
        const float4* hs = (const float4*)(hD + pp*BH);
        for (int i=tid; i<4096; i+=256) ((float4*)xs)[i] = __ldcg(hs+i);
        __syncthreads();

        float a0=0.f,a1=0.f,a2=0.f,a3=0.f;
#pragma unroll 4
        for (int k=0;k<HEq;k+=4){
            float4 v0=*(const float4*)(w0+k), v1=*(const float4*)(w1+k);
            float4 v2=*(const float4*)(w2+k), v3=*(const float4*)(w3+k);
            float x0=xs[(k+0)*32+lane], x1=xs[(k+1)*32+lane];
            float x2=xs[(k+2)*32+lane], x3=xs[(k+3)*32+lane];
            a0 += v0.x*x0+v0.y*x1+v0.z*x2+v0.w*x3;
            a1 += v1.x*x0+v1.y*x1+v1.z*x2+v1.w*x3;
            a2 += v2.x*x0+v2.y*x1+v2.z*x2+v2.w*x3;
            a3 += v3.x*x0+v3.y*x1+v3.z*x2+v3.w*x3;
        }
        const int t = dir ? (Sq-1-s) : s;
        const float* xr = xgT + (((size_t)dir*Sq + t)*Gq)*32;
        float gi = a0 + xr[(0*HEq+h_idx)*32 + lane];
        float gf = a1 + xr[(1*HEq+h_idx)*32 + lane];
        float gg = a2 + xr[(2*HEq+h_idx)*32 + lane];
        float go = a3 + xr[(3*HEq+h_idx)*32 + lane];
        float co = __ldcg(&cD[pp*BH + h_idx*32 + lane]);
        float c2 = sigf(gf)*co + sigf(gi)*tanhf(gg);
        float h2 = sigf(go)*tanhf(c2);
        bool valid = t < len;
        float hp = xs[h_idx*32+lane];
        __stcg(&hD[po*BH + h_idx*32 + lane], valid ? h2 : hp);
        __stcg(&cD[po*BH + h_idx*32 + lane], valid ? c2 : co);
        outp[((size_t)lane*Sq + t)*EDq + dir*HEq + h_idx] = valid ? h2 : 0.f;
        gbar(dir, 64, base, s+1);
    }
}

// bridge
__global__ __launch_bounds__(256) void k_bridge(
    const float* __restrict__ hW, const float* __restrict__ hb,
    const float* __restrict__ cW, const float* __restrict__ cb,
    const float* __restrict__ ehT, const float* __restrict__ ecT,
    float* __restrict__ dh, float* __restrict__ dc)
{
    const int b = blockIdx.x, l = blockIdx.y, tid = threadIdx.x;
    __shared__ float hh[EDq], cc[EDq];
    for (int i=tid;i<HEq;i+=256){
        hh[i]     = ehT[(size_t)(l*4+0)*BH + i*32 + b];
        hh[HEq+i] = ehT[(size_t)(l*4+2)*BH + i*32 + b];
        cc[i]     = ecT[(size_t)(l*4+0)*BH + i*32 + b];
        cc[HEq+i] = ecT[(size_t)(l*4+2)*BH + i*32 + b];
    }
    __syncthreads();
    const int w = tid>>5, lane = tid&31;
    for (int j=w;j<HEq;j+=8){
        const float* rh = hW + (size_t)j*EDq;
        const float* rc = cW + (size_t)j*EDq;
        float ah=0.f, ac=0.f;
        for (int k=lane;k<EDq;k+=32){ ah += rh[k]*hh[k]; ac += rc[k]*cc[k]; }
        ah = wsum(ah); ac = wsum(ac);
        if (lane==0){
            float hv = tanhf(ah + hb[j]);
            float cv = tanhf(ac + cb[j]);
            if (l==0){ dh[j*32+b]=hv; dc[j*32+b]=cv; }
            else {
#pragma unroll
                for (int q=1;q<4;q++){ dh[(size_t)q*BH + j*32 + b]=hv; dc[(size_t)q*BH + j*32 + b]=cv; }
            }
        }
    }
}

// ---------- persistent decoder: 128 blocks, spread-counter barrier ----------
#define DEC_SMEM 168832

__device__ __forceinline__ void stage2(uint4* dst, const unsigned* hsrc,
                                       const unsigned* lsrc, int tid){
    const uint4* h4 = (const uint4*)hsrc;
    const uint4* l4 = (const uint4*)lsrc;
    for (int i=tid; i<2048; i+=512){
        dst[i]      = __ldcg(h4+i);
        dst[2048+i] = __ldcg(l4+i);
    }
}

__global__ __launch_bounds__(512) void dec_all(
    const float* __restrict__ egT, const int* __restrict__ src,
    const float* __restrict__ enc, const float* __restrict__ encA,
    const float* __restrict__ db,
    const float* __restrict__ bh_, const float* __restrict__ bc_,
    float* __restrict__ feat)
{
    extern __shared__ char smc[];
    unsigned* sx  = (unsigned*)smc;
    uint4*    sx4 = (uint4*)smc;
    float* red    = (float*)(smc + 131072);
    float* gg     = (float*)(smc + 163840);
    float* hbuf   = (float*)(smc + 165888);
    float* ssc    = (float*)(smc + 166400);
    float* sh3    = (float*)(smc + 166784);

    const int tid = threadIdx.x, w = tid>>5, lane = tid&31;
    const int bk = blockIdx.x;
    const int nb_ = lane>>2;
    const int wofs[4] = {0, 3145728, 5242880, 7340032};

    unsigned bi = 0;

    // ---- init: c to regs, pack bridge h, h3 for t=0 ----
    float c_reg[4];
    if (tid < 128){
        int hl = tid>>5, b = tid&31, h = bk*4+hl;
#pragma unroll
        for (int l=0;l<4;l++) c_reg[l] = __ldcg(&bc_[(size_t)l*BH + h*32 + b]);
    }
    for (int l=0;l<4;l++){
        if (tid < 128){
            int hl = tid>>5, b = tid&31, h = bk*4+hl;
            float hv = __ldcg(&bh_[(size_t)l*BH + h*32 + b]);
            hbuf[tid] = hv;
            if (l==3) __stcg(&g_dh3[h*32 + b], hv);
        }
        __syncthreads();
        if (tid < 64){
            int p = tid>>5, b = tid&31;
            float f0 = hbuf[(2*p)*32+b], f1 = hbuf[(2*p+1)*32+b];
            __nv_bfloat16 h0=__float2bfloat16_rn(f0), h1=__float2bfloat16_rn(f1);
            float r0 = f0-__bfloat162float(h0), r1 = f1-__bfloat162float(h1);
            unsigned hi = (unsigned)__bfloat16_as_ushort(h0) | ((unsigned)__bfloat16_as_ushort(h1)<<16);
            unsigned lo = (unsigned)__bfloat16_as_ushort(__float2bfloat16_rn(r0))
                        | ((unsigned)__bfloat16_as_ushort(__float2bfloat16_rn(r1))<<16);
            int j = bk*2 + p;
            __stcg(&g_hx[((0*4+l)*2+0)*8192 + j*32 + b], hi);
            __stcg(&g_hx[((0*4+l)*2+1)*8192 + j*32 + b], lo);
        }
        __syncthreads();
    }
    dbar(bk, ++bi);

    for (int t=0; t<TD; t++){
        const int pi = t&1, po = pi^1;

        // ===== phase A: stage h0(pi), layer0 h-chunk partials =====
        stage2(sx4, g_hx+((pi*4+0)*2+0)*8192, g_hx+((pi*4+0)*2+1)*8192, tid);
        __syncthreads();

        float acc[4][4];
#pragma unroll
        for (int nt=0;nt<4;nt++)
#pragma unroll
            for (int ci=0;ci<4;ci++) acc[nt][ci]=0.f;

        const unsigned* wb0 = g_wf + (size_t)bk*96*256 + lane*4;
#pragma unroll
        for (int kk=0;kk<2;kk++){
            int ks  = 64 + w*2 + kk;
            int ksl = w*2 + kk;
            const unsigned* ap = wb0 + (size_t)ks*256;
            unsigned ah[4], al[4];
            *(uint4*)ah = *(const uint4*)ap;
            *(uint4*)al = *(const uint4*)(ap+128);
            int j0 = ksl*8 + (lane&3);
#pragma unroll
            for (int nt=0;nt<4;nt++){
                int n = nt*8 + nb_;
                unsigned bhf[2] = { sx[j0*32+n], sx[(j0+4)*32+n] };
                unsigned blf[2] = { sx[8192+j0*32+n], sx[8192+(j0+4)*32+n] };
                mma16816(acc[nt], ah, bhf);
                mma16816(acc[nt], ah, blf);
                mma16816(acc[nt], al, bhf);
            }
        }

        // ===== phase B: attention (blocks 0..31) =====
        if (bk < 32){
            const int b = bk;
            if (t==0) sh3[tid] = __ldcg(&g_dh3[tid*32 + b]);
            else      sh3[tid] = __ldcg(&feat[((size_t)(t-1)*32+b)*PKq + tid]);
            __syncthreads();
            const float4* s4 = (const float4*)sh3;
            for (int s=w;s<Sq;s+=16){
                const float4* er = (const float4*)(encA + (size_t)(b*Sq+s)*HEq);
                float v=0.f;
                for (int k4=lane;k4<128;k4+=32){
                    float4 q = er[k4]; float4 hq = s4[k4];
                    v += q.x*hq.x + q.y*hq.y + q.z*hq.z + q.w*hq.w;
                }
                v = wsum(v);
                if (lane==0) ssc[s] = (src[b*Sq+s]==0) ? -1e30f : v;
            }
            __syncthreads();
            if (w==0){
                float m=-1e30f;
                for (int i=lane;i<Sq;i+=32) m = fmaxf(m, ssc[i]);
                m = wmax(m);
                float sum=0.f;
                for (int i=lane;i<Sq;i+=32){ float e=__expf(ssc[i]-m); ssc[i]=e; sum+=e; }
                sum = wsum(sum);
                float inv = 1.f/sum;
                for (int i=lane;i<Sq;i+=32) ssc[i] *= inv;
            }
            __syncthreads();
            {
                int e0 = tid*2;
                float a0=0.f, a1=0.f;
                const float* er = enc + (size_t)b*Sq*EDq + e0;
#pragma unroll 4
                for (int s=0;s<Sq;s++){ float ww = ssc[s]; a0 += ww*er[(size_t)s*EDq]; a1 += ww*er[(size_t)s*EDq+1]; }
                float* fp = feat + ((size_t)t*32+b)*PKq + HEq + e0;
                fp[0]=a0; fp[1]=a1;
                __nv_bfloat16 h0=__float2bfloat16_rn(a0), h1=__float2bfloat16_rn(a1);
                float r0 = a0-__bfloat162float(h0), r1 = a1-__bfloat162float(h1);
                unsigned hi = (unsigned)__bfloat16_as_ushort(h0) | ((unsigned)__bfloat16_as_ushort(h1)<<16);
                unsigned lo = (unsigned)__bfloat16_as_ushort(__float2bfloat16_rn(r0))
                            | ((unsigned)__bfloat16_as_ushort(__float2bfloat16_rn(r1))<<16);
                __stcg(&g_cx[0*16384 + tid*32 + b], hi);
                __stcg(&g_cx[1*16384 + tid*32 + b], lo);
            }
        }
        dbar(bk, ++bi);

        // ===== phase C: layer0 ctx chunks =====
        stage2(sx4,      g_cx,        g_cx+16384, tid);
        stage2(sx4+4096, g_cx+8192,   g_cx+24576, tid);
        __syncthreads();
#pragma unroll
        for (int kk=0;kk<4;kk++){
            int ks  = w*4 + kk;
            int v_  = ks>>5, ksl = ks&31;
            const unsigned* ap = wb0 + (size_t)ks*256;
            unsigned ah[4], al[4];
            *(uint4*)ah = *(const uint4*)ap;
            *(uint4*)al = *(const uint4*)(ap+128);
            const unsigned* bh_p = sx + v_*16384;
            const unsigned* bl_p = bh_p + 8192;
            int j0 = ksl*8 + (lane&3);
#pragma unroll
            for (int nt=0;nt<4;nt++){
                int n = nt*8 + nb_;
                unsigned bhf[2] = { bh_p[j0*32+n], bh_p[(j0+4)*32+n] };
                unsigned blf[2] = { bl_p[j0*32+n], bl_p[(j0+4)*32+n] };
                mma16816(acc[nt], ah, bhf);
                mma16816(acc[nt], ah, blf);
                mma16816(acc[nt], al, bhf);
            }
        }
        // reduce + gates, layer 0
        __syncthreads();
#pragma unroll
        for (int nt=0;nt<4;nt++)
#pragma unroll
            for (int ci=0;ci<4;ci++)
                red[w*512 + (nt*4+ci)*32 + lane] = acc[nt][ci];
        __syncthreads();
        {
            float v=0.f;
#pragma unroll
            for (int w2=0;w2<16;w2++) v += red[w2*512 + tid];
            int q = tid>>5, ln = tid&31;
            int nt = q>>2, ci = q&3;
            int r = (ln>>2) + 8*(ci>>1);
            int n = nt*8 + (ln&3)*2 + (ci&1);
            gg[r*32+n] = v;
        }
        __syncthreads();
        if (tid < 128){
            int hl = tid>>5, b = tid&31, h = bk*4+hl;
            float gi = gg[(hl*4+0)*32+b], gf = gg[(hl*4+1)*32+b];
            float gc = gg[(hl*4+2)*32+b], go = gg[(hl*4+3)*32+b];
            const float* gp = egT + ((size_t)t*Gq)*32;
            gi += gp[(0*HEq+h)*32+b]; gf += gp[(1*HEq+h)*32+b];
            gc += gp[(2*HEq+h)*32+b]; go += gp[(3*HEq+h)*32+b];
            float c2 = sigf(gf)*c_reg[0] + sigf(gi)*tanhf(gc);
            float h2 = sigf(go)*tanhf(c2);
            c_reg[0] = c2;
            hbuf[tid] = h2;
        }
        __syncthreads();
        if (tid < 64){
            int p = tid>>5, b = tid&31;
            float f0 = hbuf[(2*p)*32+b], f1 = hbuf[(2*p+1)*32+b];
            __nv_bfloat16 h0=__float2bfloat16_rn(f0), h1=__float2bfloat16_rn(f1);
            float r0 = f0-__bfloat162float(h0), r1 = f1-__bfloat162float(h1);
            unsigned hi = (unsigned)__bfloat16_as_ushort(h0) | ((unsigned)__bfloat16_as_ushort(h1)<<16);
            unsigned lo = (unsigned)__bfloat16_as_ushort(__float2bfloat16_rn(r0))
                        | ((unsigned)__bfloat16_as_ushort(__float2bfloat16_rn(r1))<<16);
            int j = bk*2 + p;
            __stcg(&g_hx[((po*4+0)*2+0)*8192 + j*32 + b], hi);
            __stcg(&g_hx[((po*4+0)*2+1)*8192 + j*32 + b], lo);
        }
        dbar(bk, ++bi);

        // ===== layers 1..3 =====
        for (int l=1; l<4; l++){
            stage2(sx4,      g_hx+((po*4+(l-1))*2+0)*8192, g_hx+((po*4+(l-1))*2+1)*8192, tid);
            stage2(sx4+4096, g_hx+((pi*4+l)*2+0)*8192,     g_hx+((pi*4+l)*2+1)*8192,     tid);
            __syncthreads();
#pragma unroll
            for (int nt=0;nt<4;nt++)
#pragma unroll
                for (int ci=0;ci<4;ci++) acc[nt][ci]=0.f;

            const unsigned* wb = g_wf + wofs[l] + (size_t)bk*64*256 + lane*4;
#pragma unroll
            for (int kk=0;kk<4;kk++){
                int ks  = w*4 + kk;
                int v_  = ks>>5, ksl = ks&31;
                const unsigned* ap = wb + (size_t)ks*256;
                unsigned ah[4], al[4];
                *(uint4*)ah = *(const uint4*)ap;
                *(uint4*)al = *(const uint4*)(ap+128);
                const unsigned* bh_p = sx + v_*16384;
                const unsigned* bl_p = bh_p + 8192;
                int j0 = ksl*8 + (lane&3);
#pragma unroll
                for (int nt=0;nt<4;nt++){
                    int n = nt*8 + nb_;
                    unsigned bhf[2] = { bh_p[j0*32+n], bh_p[(j0+4)*32+n] };
                    unsigned blf[2] = { bl_p[j0*32+n], bl_p[(j0+4)*32+n] };
                    mma16816(acc[nt], ah, bhf);
                    mma16816(acc[nt], ah, blf);
                    mma16816(acc[nt], al, bhf);
                }
            }
            __syncthreads();
#pragma unroll
            for (int nt=0;nt<4;nt++)
#pragma unroll
                for (int ci=0;ci<4;ci++)
                    red[w*512 + (nt*4+ci)*32 + lane] = acc[nt][ci];
            __syncthreads();
            {
                float v=0.f;
#pragma unroll
                for (int w2=0;w2<16;w2++) v += red[w2*512 + tid];
                int q = tid>>5, ln = tid&31;
                int nt = q>>2, ci = q&3;
                int r = (ln>>2) + 8*(ci>>1);
                int n = nt*8 + (ln&3)*2 + (ci&1);
                gg[r*32+n] = v;
            }
            __syncthreads();
            if (tid < 128){
                int hl = tid>>5, b = tid&31, h = bk*4+hl;
                float gi = gg[(hl*4+0)*32+b], gf = gg[(hl*4+1)*32+b];
                float gc = gg[(hl*4+2)*32+b], go = gg[(hl*4+3)*32+b];
                const float* bp = db + (size_t)(l-1)*Gq;
                gi += bp[h]; gf += bp[HEq+h]; gc += bp[2*HEq+h]; go += bp[3*HEq+h];
                float c2 = sigf(gf)*c_reg[l] + sigf(gi)*tanhf(gc);
                float h2 = sigf(go)*tanhf(c2);
                c_reg[l] = c2;
                hbuf[tid] = h2;
                if (l==3) feat[((size_t)t*32+b)*PKq + h] = h2;
            }
            __syncthreads();
            if (tid < 64){
                int p = tid>>5, b = tid&31;
                float f0 = hbuf[(2*p)*32+b], f1 = hbuf[(2*p+1)*32+b];
                __nv_bfloat16 h0=__float2bfloat16_rn(f0), h1=__float2bfloat16_rn(f1);
                float r0 = f0-__bfloat162float(h0), r1 = f1-__bfloat162float(h1);
                unsigned hi = (unsigned)__bfloat16_as_ushort(h0) | ((unsigned)__bfloat16_as_ushort(h1)<<16);
                unsigned lo = (unsigned)__bfloat16_as_ushort(__float2bfloat16_rn(r0))
                            | ((unsigned)__bfloat16_as_ushort(__float2bfloat16_rn(r1))<<16);
                int j = bk*2 + p;
                __stcg(&g_hx[((po*4+l)*2+0)*8192 + j*32 + b], hi);
                __stcg(&g_hx[((po*4+l)*2+1)*8192 + j*32 + b], lo);
            }
            dbar(bk, ++bi);
        }
    }
}

static float* sym(const void* s){
    void* p = 0;
    cudaGetSymbolAddress(&p, s);
    return (float*)p;
}

extern "C" void kernel_launch(void* const* d_in, const int* in_sizes, int n_in,
                              void* d_out, int out_size)
{
    const int*   src     = (const int*)  d_in[0];
    const int*   lens    = (const int*)  d_in[1];
    const int*   tgt     = (const int*)  d_in[2];
    const float* enc_emb = (const float*)d_in[3];
    const float* eWih0   = (const float*)d_in[4];
    const float* eWhh0   = (const float*)d_in[5];
    const float* eb0     = (const float*)d_in[6];
    const float* eWih1   = (const float*)d_in[7];
    const float* eWhh1   = (const float*)d_in[8];
    const float* eb1     = (const float*)d_in[9];
    const float* brhW    = (const float*)d_in[10];
    const float* brhb    = (const float*)d_in[11];
    const float* brcW    = (const float*)d_in[12];
    const float* brcb    = (const float*)d_in[13];
    const float* dec_emb = (const float*)d_in[14];
    const float* dWih0   = (const float*)d_in[15];
    const float* dWhh0   = (const float*)d_in[16];
    const float* db0     = (const float*)d_in[17];
    const float* dWih    = (const float*)d_in[18];
    const float* dWhh    = (const float*)d_in[19];
    const float* db      = (const float*)d_in[20];
    const float* attn_W  = (const float*)d_in[21];
    const float* proj_W  = (const float*)d_in[22];
    const float* proj_b  = (const float*)d_in[23];
    float* out = (float*)d_out;

    float *emb = sym(g_emb), *xg = sym(g_xg), *xgT = sym(g_xgT);
    float *x1 = sym(g_x1), *enc = sym(g_enc), *encA = sym(g_encA);
    float *aWT = sym(g_aWT), *bzero = sym(g_bzero);
    float *eh  = sym(g_eh),  *ec = sym(g_ec), *dh = sym(g_dh), *dc = sym(g_dc);
    float *embd= sym(g_embd),*eg = sym(g_eg), *egT = sym(g_egT), *feat = sym(g_feat);
    unsigned *wf = (unsigned*)sym(g_wf);

    cudaFuncSetAttribute(enc_layer, cudaFuncAttributeMaxDynamicSharedMemorySize, 131072);
    cudaFuncSetAttribute(dec_all,   cudaFuncAttributeMaxDynamicSharedMemorySize, DEC_SMEM);

    // decoder weight fragments + attn_W transpose (independent of encoder)
    k_wf<<<4608, 256>>>(dWih0, dWhh0, dWih, dWhh, wf);
    k_aT<<<dim3(16,32), 256>>>(attn_W, aWT);

    // encoder
    k_embed_src<<<Bq*Sq, 256>>>(src, enc_emb, emb);
    k_zero<<<512, 256>>>(eh, ec, 8*BH);
    for (int d=0; d<2; d++)
        hgemm_split<<<dim3(16,24),256>>>(emb,Eq, eWih0+(size_t)d*Gq*Eq,Eq, eb0+d*Gq,
                                         xg+(size_t)d*XGS, Bq*Sq, Gq, Eq, 0);
    k_xT<<<2*Sq*64, 256>>>(xg, xgT);
    enc_layer<<<128,256,131072>>>(xgT, eWhh0, lens, eh, ec, x1);
    for (int d=0; d<2; d++)
        hgemm_split<<<dim3(16,24),256>>>(x1,EDq, eWih1+(size_t)d*Gq*EDq,EDq, eb1+d*Gq,
                                         xg+(size_t)d*XGS, Bq*Sq, Gq, EDq, 0);
    k_xT<<<2*Sq*64, 256>>>(xg, xgT);
    enc_layer<<<128,256,131072>>>(xgT, eWhh1, lens, eh+4*BH, ec+4*BH, enc);

    // encA = enc @ attn_W^T
    hgemm_split<<<dim3(4,24),256>>>(enc,EDq, aWT,EDq, bzero, encA, Bq*Sq, HEq, EDq, 0);

    // bridge + decoder precompute
    k_bridge<<<dim3(32,2),256>>>(brhW, brhb, brcW, brcb, eh, ec, dh, dc);
    k_embed_tgt<<<TD*Bq, 256>>>(tgt, dec_emb, embd);
    hgemm_split<<<dim3(16,16),256>>>(embd,Eq, dWih0,Eq+EDq, db0, eg, TD*Bq, Gq, Eq, 0);
    k_egT<<<TD*64, 256>>>(eg, egT);

    // reset decoder barrier, then full decoder (persistent, 128 blocks)
    k_rst<<<1, 32>>>();
    dec_all<<<128,512,DEC_SMEM>>>(egT, src, enc, encA, db, dh, dc, feat);

    // projection
    hgemm_split<<<dim3(125,16),256>>>(feat,PKq, proj_W,PKq, proj_b, out,
                                      TD*Bq, VTq, PKq, 1);
    (void)in_sizes; (void)n_in; (void)out_size;
}

// round 15
// speedup vs baseline: 1.0351x; 1.0351x over previous
#include <cuda_runtime.h>
#include <cuda_bf16.h>
#include <cstdint>

#define Bq   32
#define Sq   96
#define TD   63
#define Tq   64
#define Eq   256
#define HEq  512
#define Gq   2048
#define EDq  1024
#define VTq  16000
#define PKq  1536
#define BH   16384
#define XGS  6291456   // B*S*G

__device__ __align__(16) float g_emb [Bq*Sq*Eq];
__device__ __align__(16) float g_xg  [2*XGS];
__device__ __align__(16) float g_xgT [2*XGS];
__device__ __align__(16) float g_x1  [Bq*Sq*EDq];
__device__ __align__(16) float g_enc [Bq*Sq*EDq];
__device__ __align__(16) float g_encA[Bq*Sq*HEq];
__device__ __align__(16) float g_aWT [HEq*EDq];
__device__ __align__(16) float g_bzero[512];        // stays zero (never written)
__device__ __align__(16) float g_eh  [8*BH];
__device__ __align__(16) float g_ec  [8*BH];
__device__ __align__(16) float g_dh  [4*BH];
__device__ __align__(16) float g_dc  [4*BH];
__device__ __align__(16) float g_embd[TD*Bq*Eq];
__device__ __align__(16) float g_eg  [TD*Bq*Gq];
__device__ __align__(16) float g_egT [TD*Bq*Gq];
__device__ __align__(16) float g_feat[TD*Bq*PKq];
__device__ __align__(16) float g_dh3 [HEq*Bq];
__device__ __align__(16) unsigned g_hx [2*4*2*8192];
__device__ __align__(16) unsigned g_cx [2*16384];
__device__ __align__(16) unsigned g_wf [9437184];

__device__ unsigned g_cnt[4];
__device__ unsigned g_gen[4];
__device__ unsigned g_dcnt;
__device__ unsigned g_dgen;

__device__ __forceinline__ float sigf(float x){ return 1.f/(1.f + __expf(-x)); }
__device__ __forceinline__ float wsum(float v){
#pragma unroll
    for (int o=16;o;o>>=1) v += __shfl_xor_sync(0xffffffffu,v,o);
    return v;
}
__device__ __forceinline__ float wmax(float v){
#pragma unroll
    for (int o=16;o;o>>=1) v = fmaxf(v,__shfl_xor_sync(0xffffffffu,v,o));
    return v;
}

__device__ __forceinline__ unsigned atom_add_acqrel(unsigned* p, unsigned v){
    unsigned o;
    asm volatile("atom.acq_rel.gpu.global.add.u32 %0,[%1],%2;"
                 : "=r"(o) : "l"(p), "r"(v) : "memory");
    return o;
}
__device__ __forceinline__ unsigned ld_acq(const unsigned* p){
    unsigned v;
    asm volatile("ld.acquire.gpu.global.u32 %0,[%1];" : "=r"(v) : "l"(p) : "memory");
    return v;
}

// legacy single-counter barrier (encoder)
__device__ __forceinline__ void gbar(int id, unsigned nb, unsigned base, unsigned idx){
    __syncthreads();
    if (threadIdx.x == 0){
        if (atom_add_acqrel(&g_cnt[id], 1u) == nb-1u){
            atomicExch(&g_cnt[id], 0u);
            atom_add_acqrel(&g_gen[id], 1u);
        } else {
            while (ld_acq(&g_gen[id]) - base < idx) { }
        }
    }
    __syncthreads();
}

// reset decoder barrier state before every dec_all launch (stream-ordered)
__global__ void k_rst(){
    if (threadIdx.x == 0){ g_dcnt = 0u; g_dgen = 0u; }
}

// decoder barrier: single counter, ABSOLUTE thresholds (zeroed each launch).
// the (128*idx)-th arrival releases generation idx. no reset, no race.
#define DNB 128u
__device__ __forceinline__ void dbar(unsigned idx){
    __syncthreads();
    if (threadIdx.x == 0){
        unsigned a = atom_add_acqrel(&g_dcnt, 1u);
        if (a == DNB*idx - 1u) atom_add_acqrel(&g_dgen, 1u);
        while (ld_acq(&g_dgen) < idx) { }
    }
    __syncthreads();
}

__global__ void k_zero(float* a, float* b, int n){
    int i = blockIdx.x*256 + threadIdx.x;
    if (i < n){ a[i]=0.f; b[i]=0.f; }
}

__global__ void k_embed_src(const int* __restrict__ src, const float* __restrict__ emb,
                            float* __restrict__ o){
    int idx = blockIdx.x*256 + threadIdx.x;
    o[idx] = emb[(size_t)src[idx>>8]*Eq + (idx&255)];
}

__global__ void k_embed_tgt(const int* __restrict__ tgt, const float* __restrict__ emb,
                            float* __restrict__ o){
    int idx = blockIdx.x*256 + threadIdx.x;
    int m = idx>>8, t = m>>5, b = m&31;
    o[idx] = emb[(size_t)tgt[b*Tq+t]*Eq + (idx&255)];
}

__global__ __launch_bounds__(256) void k_xT(const float* __restrict__ xg,
                                            float* __restrict__ xgT){
    __shared__ float tl[32][33];
    int bid = blockIdx.x;
    int ng = bid & 63, s = (bid>>6)%Sq, dir = bid/(Sq*64);
    int n0 = ng*32;
    int nn = threadIdx.x & 31, bq = threadIdx.x >> 5;
    for (int b = bq; b < 32; b += 8)
        tl[nn][b] = xg[(size_t)dir*XGS + ((size_t)b*Sq + s)*Gq + n0 + nn];
    __syncthreads();
    int b2 = threadIdx.x & 31, n2 = threadIdx.x >> 5;
    for (int n = n2; n < 32; n += 8)
        xgT[(((size_t)dir*Sq + s)*Gq + n0 + n)*32 + b2] = tl[n][b2];
}

// eg[(t*32+b)*G + n] -> egT[(t*G + n)*32 + b]
__global__ __launch_bounds__(256) void k_egT(const float* __restrict__ eg,
                                             float* __restrict__ egT){
    __shared__ float tl[32][33];
    int bid = blockIdx.x;               // t*64 + ng
    int ng = bid & 63, t = bid >> 6;
    int n0 = ng*32;
    int nn = threadIdx.x & 31, bq = threadIdx.x >> 5;
    for (int b = bq; b < 32; b += 8)
        tl[nn][b] = eg[((size_t)t*32 + b)*Gq + n0 + nn];
    __syncthreads();
    int b2 = threadIdx.x & 31, n2 = threadIdx.x >> 5;
    for (int n = n2; n < 32; n += 8)
        egT[((size_t)t*Gq + n0 + n)*32 + b2] = tl[n][b2];
}

// attn_W [1024][512] -> aWT [512][1024]
__global__ __launch_bounds__(256) void k_aT(const float* __restrict__ A,
                                            float* __restrict__ AT){
    __shared__ float tl[32][33];
    int k0 = blockIdx.x*32, e0 = blockIdx.y*32;
    int li = threadIdx.x&31, wi = threadIdx.x>>5;
    for (int r=wi;r<32;r+=8) tl[r][li] = A[(size_t)(e0+r)*HEq + k0+li];
    __syncthreads();
    for (int r=wi;r<32;r+=8) AT[(size_t)(k0+r)*EDq + e0+li] = tl[li][r];
}

// ===== decoder weight fragment precompute =====
__global__ __launch_bounds__(256) void k_wf(
    const float* __restrict__ dWih0, const float* __restrict__ dWhh0,
    const float* __restrict__ dWih,  const float* __restrict__ dWhh,
    unsigned* __restrict__ wf)
{
    int wid = blockIdx.x*8 + (threadIdx.x>>5);
    int lane = threadIdx.x & 31;
    int l, bk, ks, KS; size_t base;
    if (wid < 128*96){ l=0; bk=wid/96; ks=wid%96; KS=96; base=0; }
    else {
        int w2 = wid - 128*96;
        l = 1 + w2/(128*64);
        int rem = w2 % (128*64);
        bk = rem/64; ks = rem%64; KS=64;
        base = 3145728 + (size_t)(l-1)*2097152;
    }
    const float* W; int ld, col0;
    if (l==0){
        if (ks<64){ W=dWih0; ld=1280; col0=256+ks*16; }
        else      { W=dWhh0; ld=512;  col0=(ks-64)*16; }
    } else {
        if (ks<32){ W=dWih + (size_t)(l-1)*Gq*HEq; ld=512; col0=ks*16; }
        else      { W=dWhh + (size_t)(l-1)*Gq*HEq; ld=512; col0=(ks-32)*16; }
    }
    int rl = lane>>2, c2 = (lane&3)*2;
    unsigned* outp = wf + base + (size_t)(bk*KS+ks)*256 + lane*4;
#pragma unroll
    for (int q=0;q<4;q++){
        int rloc = rl + ((q&1)?8:0);
        int col  = col0 + c2 + ((q&2)?8:0);
        int h = bk*4 + (rloc>>2), g = rloc&3;
        const float* wr = W + (size_t)(g*HEq + h)*ld + col;
        float f0 = wr[0], f1 = wr[1];
        __nv_bfloat16 h0=__float2bfloat16_rn(f0), h1=__float2bfloat16_rn(f1);
        float r0 = f0-__bfloat162float(h0), r1 = f1-__bfloat162float(h1);
        unsigned hi = (unsigned)__bfloat16_as_ushort(h0) | ((unsigned)__bfloat16_as_ushort(h1)<<16);
        unsigned lo = (unsigned)__bfloat16_as_ushort(__float2bfloat16_rn(r0))
                    | ((unsigned)__bfloat16_as_ushort(__float2bfloat16_rn(r1))<<16);
        outp[q] = hi;
        outp[128+q] = lo;
    }
}

// ===== split-bf16 tensor-core GEMM, cp.async pipelined =====
__device__ __forceinline__ uint32_t smaddr(const void* p){
    return (uint32_t)__cvta_generic_to_shared(p);
}
__device__ __forceinline__ void ldsm4(uint32_t* r, uint32_t a){
    asm volatile("ldmatrix.sync.aligned.m8n8.x4.shared.b16 {%0,%1,%2,%3},[%4];\n"
        : "=r"(r[0]),"=r"(r[1]),"=r"(r[2]),"=r"(r[3]) : "r"(a));
}
__device__ __forceinline__ void mma16816(float* d, const uint32_t* a, const uint32_t* b){
    asm volatile("mma.sync.aligned.m16n8k16.row.col.f32.bf16.bf16.f32 "
        "{%0,%1,%2,%3},{%4,%5,%6,%7},{%8,%9},{%0,%1,%2,%3};\n"
        : "+f"(d[0]),"+f"(d[1]),"+f"(d[2]),"+f"(d[3])
        : "r"(a[0]),"r"(a[1]),"r"(a[2]),"r"(a[3]),"r"(b[0]),"r"(b[1]));
}
__device__ __forceinline__ void cpa16(uint32_t s, const float* g){
    asm volatile("cp.async.ca.shared.global [%0],[%1],16;\n" :: "r"(s), "l"(g));
}
#define SROW 40
#define FROW 36
#define HG_SMEM (2*128*FROW*4 + 4*128*SROW*2)   // 36864 + 40960 = 77824

__device__ __forceinline__ void cvt16(const float* f, unsigned short* hD, unsigned short* lD){
    uint32_t h[8], l[8];
#pragma unroll
    for (int j=0;j<8;j++){
        float f0=f[2*j], f1=f[2*j+1];
        __nv_bfloat16 h0=__float2bfloat16_rn(f0), h1=__float2bfloat16_rn(f1);
        float l0=f0-__bfloat162float(h0), l1=f1-__bfloat162float(h1);
        __nv_bfloat16 g0=__float2bfloat16_rn(l0), g1=__float2bfloat16_rn(l1);
        h[j] = (uint32_t)__bfloat16_as_ushort(h0) | ((uint32_t)__bfloat16_as_ushort(h1)<<16);
        l[j] = (uint32_t)__bfloat16_as_ushort(g0) | ((uint32_t)__bfloat16_as_ushort(g1)<<16);
    }
    ((uint4*)hD)[0] = make_uint4(h[0],h[1],h[2],h[3]);
    ((uint4*)hD)[1] = make_uint4(h[4],h[5],h[6],h[7]);
    ((uint4*)lD)[0] = make_uint4(l[0],l[1],l[2],l[3]);
    ((uint4*)lD)[1] = make_uint4(l[4],l[5],l[6],l[7]);
}

__global__ __launch_bounds__(256,2) void hgemm_split(
    const float* __restrict__ A, int lda,
    const float* __restrict__ Bw, int ldb,
    const float* __restrict__ bias, float* __restrict__ C,
    int M, int N, int K, int permute)
{
    extern __shared__ char hsm[];
    float* Fa = (float*)hsm;                              // [128][36]
    float* Fb = (float*)(hsm + 128*FROW*4);
    unsigned short* Ah = (unsigned short*)(hsm + 2*128*FROW*4);
    unsigned short* Al = Ah + 128*SROW;
    unsigned short* Bh = Al + 128*SROW;
    unsigned short* Bl = Bh + 128*SROW;

    const int bm = blockIdx.y*128, bn = blockIdx.x*128;
    const int tid = threadIdx.x, lane = tid&31, wid = tid>>5;
    const int wm = wid&3, wn = wid>>2;

    float acc[2][8][4];
#pragma unroll
    for (int a_=0;a_<2;a_++)
#pragma unroll
        for (int b_=0;b_<8;b_++)
#pragma unroll
            for (int c_=0;c_<4;c_++) acc[a_][b_][c_]=0.f;

    const int lrow = tid>>1, lhalf = (tid&1)*16;
    int gm = bm + lrow; if (gm >= M) gm = M-1;
    const float* aG = A + (size_t)gm*lda + lhalf;
    const float* bG = Bw + (size_t)(bn+lrow)*ldb + lhalf;
    const float* fAr = Fa + lrow*FROW + lhalf;
    const float* fBr = Fb + lrow*FROW + lhalf;
    const uint32_t sFa = smaddr(fAr);
    const uint32_t sFb = smaddr(fBr);
    unsigned short* ahS = Ah + lrow*SROW + lhalf;
    unsigned short* alS = Al + lrow*SROW + lhalf;
    unsigned short* bhS = Bh + lrow*SROW + lhalf;
    unsigned short* blS = Bl + lrow*SROW + lhalf;

    const uint32_t aOff = ((uint32_t)(wm*32 + (lane&15))*SROW + (lane>>4)*8)*2;
    const uint32_t bRow = (uint32_t)(wn*64 + (lane&7) + ((lane&16)?8:0));
    const uint32_t bOff = (bRow*SROW + ((lane&8)?8:0))*2;
    const uint32_t aBh = smaddr(Ah)+aOff, aBl = smaddr(Al)+aOff;
    const uint32_t bBh = smaddr(Bh)+bOff, bBl = smaddr(Bl)+bOff;

    // preload tile 0
#pragma unroll
    for (int c=0;c<4;c++){ cpa16(sFa + c*16, aG + c*4); cpa16(sFb + c*16, bG + c*4); }
    asm volatile("cp.async.commit_group;\n" ::: "memory");
    asm volatile("cp.async.wait_group 0;\n" ::: "memory");
    __syncthreads();

    for (int k0=0; k0<K; k0+=32){
        // convert fp32 stage -> bf16 hi/lo tiles
        {
            float fb_[16];
            *(float4*)&fb_[0]  = *(const float4*)(fAr+0);
            *(float4*)&fb_[4]  = *(const float4*)(fAr+4);
            *(float4*)&fb_[8]  = *(const float4*)(fAr+8);
            *(float4*)&fb_[12] = *(const float4*)(fAr+12);
            cvt16(fb_, ahS, alS);
            *(float4*)&fb_[0]  = *(const float4*)(fBr+0);
            *(float4*)&fb_[4]  = *(const float4*)(fBr+4);
            *(float4*)&fb_[8]  = *(const float4*)(fBr+8);
            *(float4*)&fb_[12] = *(const float4*)(fBr+12);
            cvt16(fb_, bhS, blS);
        }
        __syncthreads();
        // kick off next tile's loads; they overlap with the MMA section below
        if (k0+32 < K){
#pragma unroll
            for (int c=0;c<4;c++){
                cpa16(sFa + c*16, aG + k0 + 32 + c*4);
                cpa16(sFb + c*16, bG + k0 + 32 + c*4);
            }
            asm volatile("cp.async.commit_group;\n" ::: "memory");
        }
#pragma unroll
        for (int kk=0; kk<32; kk+=16){
            uint32_t ah[2][4], al[2][4];
#pragma unroll
            for (int mt=0; mt<2; mt++){
                ldsm4(ah[mt], aBh + (mt*16*SROW + kk)*2);
                ldsm4(al[mt], aBl + (mt*16*SROW + kk)*2);
            }
#pragma unroll
            for (int ntp=0; ntp<4; ntp++){
                uint32_t bh[4], bl[4];
                ldsm4(bh, bBh + (ntp*16*SROW + kk)*2);
                ldsm4(bl, bBl + (ntp*16*SROW + kk)*2);
#pragma unroll
                for (int mt=0; mt<2; mt++){
                    float* c0 = acc[mt][ntp*2+0];
                    float* c1 = acc[mt][ntp*2+1];
                    mma16816(c0, ah[mt], bh+0);
                    mma16816(c0, ah[mt], bl+0);
                    mma16816(c0, al[mt], bh+0);
                    mma16816(c1, ah[mt], bh+2);
                    mma16816(c1, ah[mt], bl+2);
                    mma16816(c1, al[mt], bh+2);
                }
            }
        }
        asm volatile("cp.async.wait_group 0;\n" ::: "memory");
        __syncthreads();
    }

    const int mr = lane>>2, nc = (lane&3)*2;
#pragma unroll
    for (int mt=0; mt<2; mt++){
#pragma unroll
        for (int nt=0; nt<8; nt++){
            int n = bn + wn*64 + nt*8 + nc;
            float b0 = bias[n], b1 = bias[n+1];
            const float* ac = acc[mt][nt];
#pragma unroll
            for (int rr=0; rr<2; rr++){
                int m = bm + wm*32 + mt*16 + mr + rr*8;
                if (m < M){
                    size_t crow = permute ? (size_t)((m&31)*63 + (m>>5)) : (size_t)m;
                    float* cp = C + crow*(size_t)N + n;
                    cp[0] = ac[rr*2+0] + b0;
                    cp[1] = ac[rr*2+1] + b1;
                }
            }
        }
    }
}

// ---------- persistent encoder layer ----------
__global__ __launch_bounds__(256) void enc_layer(
    const float* __restrict__ xgT, const float* __restrict__ Whh,
    const int* __restrict__ lens,
    float* __restrict__ h, float* __restrict__ c,
    float* __restrict__ outp)
{
    extern __shared__ float sm[];
    float* ws = sm;
    float* xs = sm + 16384;

    const int dir = blockIdx.x >> 6, bb = blockIdx.x & 63;
    const int tid = threadIdx.x, w = tid>>5, lane = tid&31;
    const int h_idx = bb*8 + w;

    const float* wbase = Whh + (size_t)dir*Gq*HEq;
#pragma unroll
    for (int g=0; g<4; g++){
        const float4* srcp = (const float4*)(wbase + (size_t)(g*HEq + h_idx)*HEq);
        float4* dst = (float4*)(ws + (w*4+g)*HEq);
        for (int i=lane; i<128; i+=32) dst[i] = srcp[i];
    }
    __syncthreads();

    unsigned base = 0;
    if (tid == 0) base = ld_acq(&g_gen[dir]);

    const int len = lens[lane];
    float* hD = h + (size_t)dir*2*BH;
    float* cD = c + (size_t)dir*2*BH;
    const float* w0 = ws + (w*4+0)*HEq;
    const float* w1 = ws + (w*4+1)*HEq;
    const float* w2 = ws + (w*4+2)*HEq;
    const float* w3 = ws + (w*4+3)*HEq;

    for (int s=0; s<Sq; s++){
        const int pp = s&1, po = pp^1;
        const float4* hs = (const float4*)(hD + pp*BH);
        for (int i=tid; i<4096; i+=256) ((float4*)xs)[i] = __ldcg(hs+i);
        __syncthreads();

        float a0=0.f,a1=0.f,a2=0.f,a3=0.f;
#pragma unroll 4
        for (int k=0;k<HEq;k+=4){
            float4 v0=*(const float4*)(w0+k), v1=*(const float4*)(w1+k);
            float4 v2=*(const float4*)(w2+k), v3=*(const float4*)(w3+k);
            float x0=xs[(k+0)*32+lane], x1=xs[(k+1)*32+lane];
            float x2=xs[(k+2)*32+lane], x3=xs[(k+3)*32+lane];
            a0 += v0.x*x0+v0.y*x1+v0.z*x2+v0.w*x3;
            a1 += v1.x*x0+v1.y*x1+v1.z*x2+v1.w*x3;
            a2 += v2.x*x0+v2.y*x1+v2.z*x2+v2.w*x3;
            a3 += v3.x*x0+v3.y*x1+v3.z*x2+v3.w*x3;
        }
        const int t = dir ? (Sq-1-s) : s;
        const float* xr = xgT + (((size_t)dir*Sq + t)*Gq)*32;
        float gi = a0 + xr[(0*HEq+h_idx)*32 + lane];
        float gf = a1 + xr[(1*HEq+h_idx)*32 + lane];
        float gg = a2 + xr[(2*HEq+h_idx)*32 + lane];
        float go = a3 + xr[(3*HEq+h_idx)*32 + lane];
        float co = __ldcg(&cD[pp*BH + h_idx*32 + lane]);
        float c2 = sigf(gf)*co + sigf(gi)*tanhf(gg);
        float h2 = sigf(go)*tanhf(c2);
        bool valid = t < len;
        float hp = xs[h_idx*32+lane];
        __stcg(&hD[po*BH + h_idx*32 + lane], valid ? h2 : hp);
        __stcg(&cD[po*BH + h_idx*32 + lane], valid ? c2 : co);
        outp[((size_t)lane*Sq + t)*EDq + dir*HEq + h_idx] = valid ? h2 : 0.f;
        gbar(dir, 64, base, s+1);
    }
}

// bridge
__global__ __launch_bounds__(256) void k_bridge(
    const float* __restrict__ hW, const float* __restrict__ hb,
    const float* __restrict__ cW, const float* __restrict__ cb,
    const float* __restrict__ ehT, const float* __restrict__ ecT,
    float* __restrict__ dh, float* __restrict__ dc)
{
    const int b = blockIdx.x, l = blockIdx.y, tid = threadIdx.x;
    __shared__ float hh[EDq], cc[EDq];
    for (int i=tid;i<HEq;i+=256){
        hh[i]     = ehT[(size_t)(l*4+0)*BH + i*32 + b];
        hh[HEq+i] = ehT[(size_t)(l*4+2)*BH + i*32 + b];
        cc[i]     = ecT[(size_t)(l*4+0)*BH + i*32 + b];
        cc[HEq+i] = ecT[(size_t)(l*4+2)*BH + i*32 + b];
    }
    __syncthreads();
    const int w = tid>>5, lane = tid&31;
    for (int j=w;j<HEq;j+=8){
        const float* rh = hW + (size_t)j*EDq;
        const float* rc = cW + (size_t)j*EDq;
        float ah=0.f, ac=0.f;
        for (int k=lane;k<EDq;k+=32){ ah += rh[k]*hh[k]; ac += rc[k]*cc[k]; }
        ah = wsum(ah); ac = wsum(ac);
        if (lane==0){
            float hv = tanhf(ah + hb[j]);
            float cv = tanhf(ac + cb[j]);
            if (l==0){ dh[j*32+b]=hv; dc[j*32+b]=cv; }
            else {
#pragma unroll
                for (int q=1;q<4;q++){ dh[(size_t)q*BH + j*32 + b]=hv; dc[(size_t)q*BH + j*32 + b]=cv; }
            }
        }
    }
}

// ---------- persistent decoder: 128 blocks ----------
#define DEC_SMEM 168832

__device__ __forceinline__ void stage2(uint4* dst, const unsigned* hsrc,
                                       const unsigned* lsrc, int tid){
    const uint4* h4 = (const uint4*)hsrc;
    const uint4* l4 = (const uint4*)lsrc;
    for (int i=tid; i<2048; i+=512){
        dst[i]      = __ldcg(h4+i);
        dst[2048+i] = __ldcg(l4+i);
    }
}

__global__ __launch_bounds__(512) void dec_all(
    const float* __restrict__ egT, const int* __restrict__ src,
    const float* __restrict__ enc, const float* __restrict__ encA,
    const float* __restrict__ db,
    const float* __restrict__ bh_, const float* __restrict__ bc_,
    float* __restrict__ feat)
{
    extern __shared__ char smc[];
    unsigned* sx  = (unsigned*)smc;
    uint4*    sx4 = (uint4*)smc;
    float* red    = (float*)(smc + 131072);
    float* gg     = (float*)(smc + 163840);
    float* hbuf   = (float*)(smc + 165888);
    float* ssc    = (float*)(smc + 166400);
    float* sh3    = (float*)(smc + 166784);

    const int tid = threadIdx.x, w = tid>>5, lane = tid&31;
    const int bk = blockIdx.x;
    const int nb_ = lane>>2;
    const int wofs[4] = {0, 3145728, 5242880, 7340032};

    unsigned bi = 0;

    // ---- init: c to regs, pack bridge h, h3 for t=0 ----
    float c_reg[4];
    if (tid < 128){
        int hl = tid>>5, b = tid&31, h = bk*4+hl;
#pragma unroll
        for (int l=0;l<4;l++) c_reg[l] = __ldcg(&bc_[(size_t)l*BH + h*32 + b]);
    }
    for (int l=0;l<4;l++){
        if (tid < 128){
            int hl = tid>>5, b = tid&31, h = bk*4+hl;
            float hv = __ldcg(&bh_[(size_t)l*BH + h*32 + b]);
            hbuf[tid] = hv;
            if (l==3) __stcg(&g_dh3[h*32 + b], hv);
        }
        __syncthreads();
        if (tid < 64){
            int p = tid>>5, b = tid&31;
            float f0 = hbuf[(2*p)*32+b], f1 = hbuf[(2*p+1)*32+b];
            __nv_bfloat16 h0=__float2bfloat16_rn(f0), h1=__float2bfloat16_rn(f1);
            float r0 = f0-__bfloat162float(h0), r1 = f1-__bfloat162float(h1);
            unsigned hi = (unsigned)__bfloat16_as_ushort(h0) | ((unsigned)__bfloat16_as_ushort(h1)<<16);
            unsigned lo = (unsigned)__bfloat16_as_ushort(__float2bfloat16_rn(r0))
                        | ((unsigned)__bfloat16_as_ushort(__float2bfloat16_rn(r1))<<16);
            int j = bk*2 + p;
            __stcg(&g_hx[((0*4+l)*2+0)*8192 + j*32 + b], hi);
            __stcg(&g_hx[((0*4+l)*2+1)*8192 + j*32 + b], lo);
        }
        __syncthreads();
    }
    dbar(++bi);

    for (int t=0; t<TD; t++){
        const int pi = t&1, po = pi^1;

        // ===== phase A: stage h0(pi), layer0 h-chunk partials =====
        stage2(sx4, g_hx+((pi*4+0)*2+0)*8192, g_hx+((pi*4+0)*2+1)*8192, tid);
        __syncthreads();

        float acc[4][4];
#pragma unroll
        for (int nt=0;nt<4;nt++)
#pragma unroll
            for (int ci=0;ci<4;ci++) acc[nt][ci]=0.f;

        const unsigned* wb0 = g_wf + (size_t)bk*96*256 + lane*4;
#pragma unroll
        for (int kk=0;kk<2;kk++){
            int ks  = 64 + w*2 + kk;
            int ksl = w*2 + kk;
            const unsigned* ap = wb0 + (size_t)ks*256;
            unsigned ah[4], al[4];
            *(uint4*)ah = *(const uint4*)ap;
            *(uint4*)al = *(const uint4*)(ap+128);
            int j0 = ksl*8 + (lane&3);
#pragma unroll
            for (int nt=0;nt<4;nt++){
                int n = nt*8 + nb_;
                unsigned bhf[2] = { sx[j0*32+n], sx[(j0+4)*32+n] };
                unsigned blf[2] = { sx[8192+j0*32+n], sx[8192+(j0+4)*32+n] };
                mma16816(acc[nt], ah, bhf);
                mma16816(acc[nt], ah, blf);
                mma16816(acc[nt], al, bhf);
            }
        }

        // ===== phase B: attention (blocks 0..31) =====
        if (bk < 32){
            const int b = bk;
            if (t==0) sh3[tid] = __ldcg(&g_dh3[tid*32 + b]);
            else      sh3[tid] = __ldcg(&feat[((size_t)(t-1)*32+b)*PKq + tid]);
            __syncthreads();
            const float4* s4 = (const float4*)sh3;
            for (int s=w;s<Sq;s+=16){
                const float4* er = (const float4*)(encA + (size_t)(b*Sq+s)*HEq);
                float v=0.f;
                for (int k4=lane;k4<128;k4+=32){
                    float4 q = er[k4]; float4 hq = s4[k4];
                    v += q.x*hq.x + q.y*hq.y + q.z*hq.z + q.w*hq.w;
                }
                v = wsum(v);
                if (lane==0) ssc[s] = (src[b*Sq+s]==0) ? -1e30f : v;
            }
            __syncthreads();
            if (w==0){
                float m=-1e30f;
                for (int i=lane;i<Sq;i+=32) m = fmaxf(m, ssc[i]);
                m = wmax(m);
                float sum=0.f;
                for (int i=lane;i<Sq;i+=32){ float e=__expf(ssc[i]-m); ssc[i]=e; sum+=e; }
                sum = wsum(sum);
                float inv = 1.f/sum;
                for (int i=lane;i<Sq;i+=32) ssc[i] *= inv;
            }
            __syncthreads();
            {
                int e0 = tid*2;
                float a0=0.f, a1=0.f;
                const float* er = enc + (size_t)b*Sq*EDq + e0;
#pragma unroll 4
                for (int s=0;s<Sq;s++){ float ww = ssc[s]; a0 += ww*er[(size_t)s*EDq]; a1 += ww*er[(size_t)s*EDq+1]; }
                float* fp = feat + ((size_t)t*32+b)*PKq + HEq + e0;
                fp[0]=a0; fp[1]=a1;
                __nv_bfloat16 h0=__float2bfloat16_rn(a0), h1=__float2bfloat16_rn(a1);
                float r0 = a0-__bfloat162float(h0), r1 = a1-__bfloat162float(h1);
                unsigned hi = (unsigned)__bfloat16_as_ushort(h0) | ((unsigned)__bfloat16_as_ushort(h1)<<16);
                unsigned lo = (unsigned)__bfloat16_as_ushort(__float2bfloat16_rn(r0))
                            | ((unsigned)__bfloat16_as_ushort(__float2bfloat16_rn(r1))<<16);
                __stcg(&g_cx[0*16384 + tid*32 + b], hi);
                __stcg(&g_cx[1*16384 + tid*32 + b], lo);
            }
        }
        dbar(++bi);

        // ===== phase C: layer0 ctx chunks =====
        stage2(sx4,      g_cx,        g_cx+16384, tid);
        stage2(sx4+4096, g_cx+8192,   g_cx+24576, tid);
        __syncthreads();
#pragma unroll
        for (int kk=0;kk<4;kk++){
            int ks  = w*4 + kk;
            int v_  = ks>>5, ksl = ks&31;
            const unsigned* ap = wb0 + (size_t)ks*256;
            unsigned ah[4], al[4];
            *(uint4*)ah = *(const uint4*)ap;
            *(uint4*)al = *(const uint4*)(ap+128);
            const unsigned* bh_p = sx + v_*16384;
            const unsigned* bl_p = bh_p + 8192;
            int j0 = ksl*8 + (lane&3);
#pragma unroll
            for (int nt=0;nt<4;nt++){
                int n = nt*8 + nb_;
                unsigned bhf[2] = { bh_p[j0*32+n], bh_p[(j0+4)*32+n] };
                unsigned blf[2] = { bl_p[j0*32+n], bl_p[(j0+4)*32+n] };
                mma16816(acc[nt], ah, bhf);
                mma16816(acc[nt], ah, blf);
                mma16816(acc[nt], al, bhf);
            }
        }
        // reduce + gates, layer 0
        __syncthreads();
#pragma unroll
        for (int nt=0;nt<4;nt++)
#pragma unroll
            for (int ci=0;ci<4;ci++)
                red[w*512 + (nt*4+ci)*32 + lane] = acc[nt][ci];
        __syncthreads();
        {
            float v=0.f;
#pragma unroll
            for (int w2=0;w2<16;w2++) v += red[w2*512 + tid];
            int q = tid>>5, ln = tid&31;
            int nt = q>>2, ci = q&3;
            int r = (ln>>2) + 8*(ci>>1);
            int n = nt*8 + (ln&3)*2 + (ci&1);
            gg[r*32+n] = v;
        }
        __syncthreads();
        if (tid < 128){
            int hl = tid>>5, b = tid&31, h = bk*4+hl;
            float gi = gg[(hl*4+0)*32+b], gf = gg[(hl*4+1)*32+b];
            float gc = gg[(hl*4+2)*32+b], go = gg[(hl*4+3)*32+b];
            const float* gp = egT + ((size_t)t*Gq)*32;
            gi += gp[(0*HEq+h)*32+b]; gf += gp[(1*HEq+h)*32+b];
            gc += gp[(2*HEq+h)*32+b]; go += gp[(3*HEq+h)*32+b];
            float c2 = sigf(gf)*c_reg[0] + sigf(gi)*tanhf(gc);
            float h2 = sigf(go)*tanhf(c2);
            c_reg[0] = c2;
            hbuf[tid] = h2;
        }
        __syncthreads();
        if (tid < 64){
            int p = tid>>5, b = tid&31;
            float f0 = hbuf[(2*p)*32+b], f1 = hbuf[(2*p+1)*32+b];
            __nv_bfloat16 h0=__float2bfloat16_rn(f0), h1=__float2bfloat16_rn(f1);
            float r0 = f0-__bfloat162float(h0), r1 = f1-__bfloat162float(h1);
            unsigned hi = (unsigned)__bfloat16_as_ushort(h0) | ((unsigned)__bfloat16_as_ushort(h1)<<16);
            unsigned lo = (unsigned)__bfloat16_as_ushort(__float2bfloat16_rn(r0))
                        | ((unsigned)__bfloat16_as_ushort(__float2bfloat16_rn(r1))<<16);
            int j = bk*2 + p;
            __stcg(&g_hx[((po*4+0)*2+0)*8192 + j*32 + b], hi);
            __stcg(&g_hx[((po*4+0)*2+1)*8192 + j*32 + b], lo);
        }
        dbar(++bi);

        // ===== layers 1..3 =====
        for (int l=1; l<4; l++){
            stage2(sx4,      g_hx+((po*4+(l-1))*2+0)*8192, g_hx+((po*4+(l-1))*2+1)*8192, tid);
            stage2(sx4+4096, g_hx+((pi*4+l)*2+0)*8192,     g_hx+((pi*4+l)*2+1)*8192,     tid);
            __syncthreads();
#pragma unroll
            for (int nt=0;nt<4;nt++)
#pragma unroll
                for (int ci=0;ci<4;ci++) acc[nt][ci]=0.f;

            const unsigned* wb = g_wf + wofs[l] + (size_t)bk*64*256 + lane*4;
#pragma unroll
            for (int kk=0;kk<4;kk++){
                int ks  = w*4 + kk;
                int v_  = ks>>5, ksl = ks&31;
                const unsigned* ap = wb + (size_t)ks*256;
                unsigned ah[4], al[4];
                *(uint4*)ah = *(const uint4*)ap;
                *(uint4*)al = *(const uint4*)(ap+128);
                const unsigned* bh_p = sx + v_*16384;
                const unsigned* bl_p = bh_p + 8192;
                int j0 = ksl*8 + (lane&3);
#pragma unroll
                for (int nt=0;nt<4;nt++){
                    int n = nt*8 + nb_;
                    unsigned bhf[2] = { bh_p[j0*32+n], bh_p[(j0+4)*32+n] };
                    unsigned blf[2] = { bl_p[j0*32+n], bl_p[(j0+4)*32+n] };
                    mma16816(acc[nt], ah, bhf);
                    mma16816(acc[nt], ah, blf);
                    mma16816(acc[nt], al, bhf);
                }
            }
            __syncthreads();
#pragma unroll
            for (int nt=0;nt<4;nt++)
#pragma unroll
                for (int ci=0;ci<4;ci++)
                    red[w*512 + (nt*4+ci)*32 + lane] = acc[nt][ci];
            __syncthreads();
            {
                float v=0.f;
#pragma unroll
                for (int w2=0;w2<16;w2++) v += red[w2*512 + tid];
                int q = tid>>5, ln = tid&31;
                int nt = q>>2, ci = q&3;
                int r = (ln>>2) + 8*(ci>>1);
                int n = nt*8 + (ln&3)*2 + (ci&1);
                gg[r*32+n] = v;
            }
            __syncthreads();
            if (tid < 128){
                int hl = tid>>5, b = tid&31, h = bk*4+hl;
                float gi = gg[(hl*4+0)*32+b], gf = gg[(hl*4+1)*32+b];
                float gc = gg[(hl*4+2)*32+b], go = gg[(hl*4+3)*32+b];
                const float* bp = db + (size_t)(l-1)*Gq;
                gi += bp[h]; gf += bp[HEq+h]; gc += bp[2*HEq+h]; go += bp[3*HEq+h];
                float c2 = sigf(gf)*c_reg[l] + sigf(gi)*tanhf(gc);
                float h2 = sigf(go)*tanhf(c2);
                c_reg[l] = c2;
                hbuf[tid] = h2;
                if (l==3) feat[((size_t)t*32+b)*PKq + h] = h2;
            }
            __syncthreads();
            if (tid < 64){
                int p = tid>>5, b = tid&31;
                float f0 = hbuf[(2*p)*32+b], f1 = hbuf[(2*p+1)*32+b];
                __nv_bfloat16 h0=__float2bfloat16_rn(f0), h1=__float2bfloat16_rn(f1);
                float r0 = f0-__bfloat162float(h0), r1 = f1-__bfloat162float(h1);
                unsigned hi = (unsigned)__bfloat16_as_ushort(h0) | ((unsigned)__bfloat16_as_ushort(h1)<<16);
                unsigned lo = (unsigned)__bfloat16_as_ushort(__float2bfloat16_rn(r0))
                            | ((unsigned)__bfloat16_as_ushort(__float2bfloat16_rn(r1))<<16);
                int j = bk*2 + p;
                __stcg(&g_hx[((po*4+l)*2+0)*8192 + j*32 + b], hi);
                __stcg(&g_hx[((po*4+l)*2+1)*8192 + j*32 + b], lo);
            }
            dbar(++bi);
        }
    }
}

static float* sym(const void* s){
    void* p = 0;
    cudaGetSymbolAddress(&p, s);
    return (float*)p;
}

extern "C" void kernel_launch(void* const* d_in, const int* in_sizes, int n_in,
                              void* d_out, int out_size)
{
    const int*   src     = (const int*)  d_in[0];
    const int*   lens    = (const int*)  d_in[1];
    const int*   tgt     = (const int*)  d_in[2];
    const float* enc_emb = (const float*)d_in[3];
    const float* eWih0   = (const float*)d_in[4];
    const float* eWhh0   = (const float*)d_in[5];
    const float* eb0     = (const float*)d_in[6];
    const float* eWih1   = (const float*)d_in[7];
    const float* eWhh1   = (const float*)d_in[8];
    const float* eb1     = (const float*)d_in[9];
    const float* brhW    = (const float*)d_in[10];
    const float* brhb    = (const float*)d_in[11];
    const float* brcW    = (const float*)d_in[12];
    const float* brcb    = (const float*)d_in[13];
    const float* dec_emb = (const float*)d_in[14];
    const float* dWih0   = (const float*)d_in[15];
    const float* dWhh0   = (const float*)d_in[16];
    const float* db0     = (const float*)d_in[17];
    const float* dWih    = (const float*)d_in[18];
    const float* dWhh    = (const float*)d_in[19];
    const float* db      = (const float*)d_in[20];
    const float* attn_W  = (const float*)d_in[21];
    const float* proj_W  = (const float*)d_in[22];
    const float* proj_b  = (const float*)d_in[23];
    float* out = (float*)d_out;

    float *emb = sym(g_emb), *xg = sym(g_xg), *xgT = sym(g_xgT);
    float *x1 = sym(g_x1), *enc = sym(g_enc), *encA = sym(g_encA);
    float *aWT = sym(g_aWT), *bzero = sym(g_bzero);
    float *eh  = sym(g_eh),  *ec = sym(g_ec), *dh = sym(g_dh), *dc = sym(g_dc);
    float *embd= sym(g_embd),*eg = sym(g_eg), *egT = sym(g_egT), *feat = sym(g_feat);
    unsigned *wf = (unsigned*)sym(g_wf);

    cudaFuncSetAttribute(enc_layer,   cudaFuncAttributeMaxDynamicSharedMemorySize, 131072);
    cudaFuncSetAttribute(dec_all,     cudaFuncAttributeMaxDynamicSharedMemorySize, DEC_SMEM);
    cudaFuncSetAttribute(hgemm_split, cudaFuncAttributeMaxDynamicSharedMemorySize, HG_SMEM);

    // decoder weight fragments + attn_W transpose (independent of encoder)
    k_wf<<<4608, 256>>>(dWih0, dWhh0, dWih, dWhh, wf);
    k_aT<<<dim3(16,32), 256>>>(attn_W, aWT);

    // encoder
    k_embed_src<<<Bq*Sq, 256>>>(src, enc_emb, emb);
    k_zero<<<512, 256>>>(eh, ec, 8*BH);
    for (int d=0; d<2; d++)
        hgemm_split<<<dim3(16,24),256,HG_SMEM>>>(emb,Eq, eWih0+(size_t)d*Gq*Eq,Eq, eb0+d*Gq,
                                         xg+(size_t)d*XGS, Bq*Sq, Gq, Eq, 0);
    k_xT<<<2*Sq*64, 256>>>(xg, xgT);
    enc_layer<<<128,256,131072>>>(xgT, eWhh0, lens, eh, ec, x1);
    for (int d=0; d<2; d++)
        hgemm_split<<<dim3(16,24),256,HG_SMEM>>>(x1,EDq, eWih1+(size_t)d*Gq*EDq,EDq, eb1+d*Gq,
                                         xg+(size_t)d*XGS, Bq*Sq, Gq, EDq, 0);
    k_xT<<<2*Sq*64, 256>>>(xg, xgT);
    enc_layer<<<128,256,131072>>>(xgT, eWhh1, lens, eh+4*BH, ec+4*BH, enc);

    // encA = enc @ attn_W^T
    hgemm_split<<<dim3(4,24),256,HG_SMEM>>>(enc,EDq, aWT,EDq, bzero, encA, Bq*Sq, HEq, EDq, 0);

    // bridge + decoder precompute
    k_bridge<<<dim3(32,2),256>>>(brhW, brhb, brcW, brcb, eh, ec, dh, dc);
    k_embed_tgt<<<TD*Bq, 256>>>(tgt, dec_emb, embd);
    hgemm_split<<<dim3(16,16),256,HG_SMEM>>>(embd,Eq, dWih0,Eq+EDq, db0, eg, TD*Bq, Gq, Eq, 0);
    k_egT<<<TD*64, 256>>>(eg, egT);

    // reset decoder barrier, then full decoder (persistent, 128 blocks)
    k_rst<<<1, 32>>>();
    dec_all<<<128,512,DEC_SMEM>>>(egT, src, enc, encA, db, dh, dc, feat);

    // projection
    hgemm_split<<<dim3(125,16),256,HG_SMEM>>>(feat,PKq, proj_W,PKq, proj_b, out,
                                      TD*Bq, VTq, PKq, 1);
    (void)in_sizes; (void)n_in; (void)out_size;
}

// round 17
// speedup vs baseline: 1.0717x; 1.0354x over previous
#include <cuda_runtime.h>
#include <cuda_bf16.h>
#include <cstdint>

#define Bq   32
#define Sq   96
#define TD   63
#define Tq   64
#define Eq   256
#define HEq  512
#define Gq   2048
#define EDq  1024
#define VTq  16000
#define PKq  1536
#define BH   16384
#define XGS  6291456   // B*S*G

__device__ __align__(16) float g_emb [Bq*Sq*Eq];
__device__ __align__(16) float g_xg  [2*XGS];
__device__ __align__(16) float g_xgT [2*XGS];
__device__ __align__(16) float g_x1  [Bq*Sq*EDq];
__device__ __align__(16) float g_enc [Bq*Sq*EDq];
__device__ __align__(16) float g_encA[Bq*Sq*HEq];
__device__ __align__(16) float g_aWT [HEq*EDq];
__device__ __align__(16) float g_bzero[512];
__device__ __align__(16) float g_eh  [8*BH];
__device__ __align__(16) float g_ec  [8*BH];
__device__ __align__(16) float g_dh  [4*BH];
__device__ __align__(16) float g_dc  [4*BH];
__device__ __align__(16) float g_embd[TD*Bq*Eq];
__device__ __align__(16) float g_eg  [TD*Bq*Gq];
__device__ __align__(16) float g_egT [TD*Bq*Gq];
__device__ __align__(16) float g_feat[TD*Bq*PKq];
__device__ __align__(16) float g_dh3 [HEq*Bq];
__device__ __align__(16) unsigned g_hx [2*4*2*8192];
__device__ __align__(16) unsigned g_cx [2*16384];
__device__ __align__(16) unsigned g_wf [9437184];

__device__ unsigned g_cnt[4];
__device__ unsigned g_gen[4];

__device__ __forceinline__ float sigf(float x){ return 1.f/(1.f + __expf(-x)); }
__device__ __forceinline__ float wsum(float v){
#pragma unroll
    for (int o=16;o;o>>=1) v += __shfl_xor_sync(0xffffffffu,v,o);
    return v;
}
__device__ __forceinline__ float wmax(float v){
#pragma unroll
    for (int o=16;o;o>>=1) v = fmaxf(v,__shfl_xor_sync(0xffffffffu,v,o));
    return v;
}

__device__ __forceinline__ unsigned atom_add_acqrel(unsigned* p, unsigned v){
    unsigned o;
    asm volatile("atom.acq_rel.gpu.global.add.u32 %0,[%1],%2;"
                 : "=r"(o) : "l"(p), "r"(v) : "memory");
    return o;
}
__device__ __forceinline__ unsigned ld_acq(const unsigned* p){
    unsigned v;
    asm volatile("ld.acquire.gpu.global.u32 %0,[%1];" : "=r"(v) : "l"(p) : "memory");
    return v;
}

__device__ __forceinline__ void gbar_arrive(int id, unsigned nb){
    __syncthreads();
    if (threadIdx.x == 0){
        if (atom_add_acqrel(&g_cnt[id], 1u) == nb-1u){
            atomicExch(&g_cnt[id], 0u);
            atom_add_acqrel(&g_gen[id], 1u);
        }
    }
}
__device__ __forceinline__ void gbar_wait(int id, unsigned base, unsigned idx){
    if (threadIdx.x == 0){
        while (ld_acq(&g_gen[id]) - base < idx) { }
    }
    __syncthreads();
}
__device__ __forceinline__ void gbar(int id, unsigned nb, unsigned base, unsigned idx){
    gbar_arrive(id, nb);
    gbar_wait(id, base, idx);
}

__global__ void k_zero(float* a, float* b, int n){
    int i = blockIdx.x*256 + threadIdx.x;
    if (i < n){ a[i]=0.f; b[i]=0.f; }
}

__global__ void k_embed_src(const int* __restrict__ src, const float* __restrict__ emb,
                            float* __restrict__ o){
    int idx = blockIdx.x*256 + threadIdx.x;
    o[idx] = emb[(size_t)src[idx>>8]*Eq + (idx&255)];
}

__global__ void k_embed_tgt(const int* __restrict__ tgt, const float* __restrict__ emb,
                            float* __restrict__ o){
    int idx = blockIdx.x*256 + threadIdx.x;
    int m = idx>>8, t = m>>5, b = m&31;
    o[idx] = emb[(size_t)tgt[b*Tq+t]*Eq + (idx&255)];
}

__global__ __launch_bounds__(256) void k_xT(const float* __restrict__ xg,
                                            float* __restrict__ xgT){
    __shared__ float tl[32][33];
    int bid = blockIdx.x;
    int ng = bid & 63, s = (bid>>6)%Sq, dir = bid/(Sq*64);
    int n0 = ng*32;
    int nn = threadIdx.x & 31, bq = threadIdx.x >> 5;
    for (int b = bq; b < 32; b += 8)
        tl[nn][b] = xg[(size_t)dir*XGS + ((size_t)b*Sq + s)*Gq + n0 + nn];
    __syncthreads();
    int b2 = threadIdx.x & 31, n2 = threadIdx.x >> 5;
    for (int n = n2; n < 32; n += 8)
        xgT[(((size_t)dir*Sq + s)*Gq + n0 + n)*32 + b2] = tl[n][b2];
}

// eg[(t*32+b)*G + n] -> egT[(t*G + n)*32 + b]
__global__ __launch_bounds__(256) void k_egT(const float* __restrict__ eg,
                                             float* __restrict__ egT){
    __shared__ float tl[32][33];
    int bid = blockIdx.x;
    int ng = bid & 63, t = bid >> 6;
    int n0 = ng*32;
    int nn = threadIdx.x & 31, bq = threadIdx.x >> 5;
    for (int b = bq; b < 32; b += 8)
        tl[nn][b] = eg[((size_t)t*32 + b)*Gq + n0 + nn];
    __syncthreads();
    int b2 = threadIdx.x & 31, n2 = threadIdx.x >> 5;
    for (int n = n2; n < 32; n += 8)
        egT[((size_t)t*Gq + n0 + n)*32 + b2] = tl[n][b2];
}

// attn_W [1024][512] -> aWT [512][1024]
__global__ __launch_bounds__(256) void k_aT(const float* __restrict__ A,
                                            float* __restrict__ AT){
    __shared__ float tl[32][33];
    int k0 = blockIdx.x*32, e0 = blockIdx.y*32;
    int li = threadIdx.x&31, wi = threadIdx.x>>5;
    for (int r=wi;r<32;r+=8) tl[r][li] = A[(size_t)(e0+r)*HEq + k0+li];
    __syncthreads();
    for (int r=wi;r<32;r+=8) AT[(size_t)(k0+r)*EDq + e0+li] = tl[li][r];
}

// ===== decoder weight fragment precompute =====
__global__ __launch_bounds__(256) void k_wf(
    const float* __restrict__ dWih0, const float* __restrict__ dWhh0,
    const float* __restrict__ dWih,  const float* __restrict__ dWhh,
    unsigned* __restrict__ wf)
{
    int wid = blockIdx.x*8 + (threadIdx.x>>5);
    int lane = threadIdx.x & 31;
    int l, bk, ks, KS; size_t base;
    if (wid < 128*96){ l=0; bk=wid/96; ks=wid%96; KS=96; base=0; }
    else {
        int w2 = wid - 128*96;
        l = 1 + w2/(128*64);
        int rem = w2 % (128*64);
        bk = rem/64; ks = rem%64; KS=64;
        base = 3145728 + (size_t)(l-1)*2097152;
    }
    const float* W; int ld, col0;
    if (l==0){
        if (ks<64){ W=dWih0; ld=1280; col0=256+ks*16; }
        else      { W=dWhh0; ld=512;  col0=(ks-64)*16; }
    } else {
        if (ks<32){ W=dWih + (size_t)(l-1)*Gq*HEq; ld=512; col0=ks*16; }
        else      { W=dWhh + (size_t)(l-1)*Gq*HEq; ld=512; col0=(ks-32)*16; }
    }
    int rl = lane>>2, c2 = (lane&3)*2;
    unsigned* outp = wf + base + (size_t)(bk*KS+ks)*256 + lane*4;
#pragma unroll
    for (int q=0;q<4;q++){
        int rloc = rl + ((q&1)?8:0);
        int col  = col0 + c2 + ((q&2)?8:0);
        int h = bk*4 + (rloc>>2), g = rloc&3;
        const float* wr = W + (size_t)(g*HEq + h)*ld + col;
        float f0 = wr[0], f1 = wr[1];
        __nv_bfloat16 h0=__float2bfloat16_rn(f0), h1=__float2bfloat16_rn(f1);
        float r0 = f0-__bfloat162float(h0), r1 = f1-__bfloat162float(h1);
        unsigned hi = (unsigned)__bfloat16_as_ushort(h0) | ((unsigned)__bfloat16_as_ushort(h1)<<16);
        unsigned lo = (unsigned)__bfloat16_as_ushort(__float2bfloat16_rn(r0))
                    | ((unsigned)__bfloat16_as_ushort(__float2bfloat16_rn(r1))<<16);
        outp[q] = hi;
        outp[128+q] = lo;
    }
}

// ===== split-bf16 tensor-core GEMM, cp.async pipelined =====
__device__ __forceinline__ uint32_t smaddr(const void* p){
    return (uint32_t)__cvta_generic_to_shared(p);
}
__device__ __forceinline__ void ldsm4(uint32_t* r, uint32_t a){
    asm volatile("ldmatrix.sync.aligned.m8n8.x4.shared.b16 {%0,%1,%2,%3},[%4];\n"
        : "=r"(r[0]),"=r"(r[1]),"=r"(r[2]),"=r"(r[3]) : "r"(a));
}
__device__ __forceinline__ void mma16816(float* d, const uint32_t* a, const uint32_t* b){
    asm volatile("mma.sync.aligned.m16n8k16.row.col.f32.bf16.bf16.f32 "
        "{%0,%1,%2,%3},{%4,%5,%6,%7},{%8,%9},{%0,%1,%2,%3};\n"
        : "+f"(d[0]),"+f"(d[1]),"+f"(d[2]),"+f"(d[3])
        : "r"(a[0]),"r"(a[1]),"r"(a[2]),"r"(a[3]),"r"(b[0]),"r"(b[1]));
}
__device__ __forceinline__ void cpa16(uint32_t s, const float* g){
    asm volatile("cp.async.ca.shared.global [%0],[%1],16;\n" :: "r"(s), "l"(g));
}
#define SROW 40
#define FROW 36
#define HG_SMEM (2*128*FROW*4 + 4*128*SROW*2)   // 77824

__device__ __forceinline__ void cvt16(const float* f, unsigned short* hD, unsigned short* lD){
    uint32_t h[8], l[8];
#pragma unroll
    for (int j=0;j<8;j++){
        float f0=f[2*j], f1=f[2*j+1];
        __nv_bfloat16 h0=__float2bfloat16_rn(f0), h1=__float2bfloat16_rn(f1);
        float l0=f0-__bfloat162float(h0), l1=f1-__bfloat162float(h1);
        __nv_bfloat16 g0=__float2bfloat16_rn(l0), g1=__float2bfloat16_rn(l1);
        h[j] = (uint32_t)__bfloat16_as_ushort(h0) | ((uint32_t)__bfloat16_as_ushort(h1)<<16);
        l[j] = (uint32_t)__bfloat16_as_ushort(g0) | ((uint32_t)__bfloat16_as_ushort(g1)<<16);
    }
    ((uint4*)hD)[0] = make_uint4(h[0],h[1],h[2],h[3]);
    ((uint4*)hD)[1] = make_uint4(h[4],h[5],h[6],h[7]);
    ((uint4*)lD)[0] = make_uint4(l[0],l[1],l[2],l[3]);
    ((uint4*)lD)[1] = make_uint4(l[4],l[5],l[6],l[7]);
}

__global__ __launch_bounds__(256,2) void hgemm_split(
    const float* __restrict__ A, int lda,
    const float* __restrict__ Bw, int ldb,
    const float* __restrict__ bias, float* __restrict__ C,
    int M, int N, int K, int permute)
{
    extern __shared__ char hsm[];
    float* Fa = (float*)hsm;
    float* Fb = (float*)(hsm + 128*FROW*4);
    unsigned short* Ah = (unsigned short*)(hsm + 2*128*FROW*4);
    unsigned short* Al = Ah + 128*SROW;
    unsigned short* Bh = Al + 128*SROW;
    unsigned short* Bl = Bh + 128*SROW;

    const int bm = blockIdx.y*128, bn = blockIdx.x*128;
    const int tid = threadIdx.x, lane = tid&31, wid = tid>>5;
    const int wm = wid&3, wn = wid>>2;

    float acc[2][8][4];
#pragma unroll
    for (int a_=0;a_<2;a_++)
#pragma unroll
        for (int b_=0;b_<8;b_++)
#pragma unroll
            for (int c_=0;c_<4;c_++) acc[a_][b_][c_]=0.f;

    const int lrow = tid>>1, lhalf = (tid&1)*16;
    int gm = bm + lrow; if (gm >= M) gm = M-1;
    const float* aG = A + (size_t)gm*lda + lhalf;
    const float* bG = Bw + (size_t)(bn+lrow)*ldb + lhalf;
    const float* fAr = Fa + lrow*FROW + lhalf;
    const float* fBr = Fb + lrow*FROW + lhalf;
    const uint32_t sFa = smaddr(fAr);
    const uint32_t sFb = smaddr(fBr);
    unsigned short* ahS = Ah + lrow*SROW + lhalf;
    unsigned short* alS = Al + lrow*SROW + lhalf;
    unsigned short* bhS = Bh + lrow*SROW + lhalf;
    unsigned short* blS = Bl + lrow*SROW + lhalf;

    const uint32_t aOff = ((uint32_t)(wm*32 + (lane&15))*SROW + (lane>>4)*8)*2;
    const uint32_t bRow = (uint32_t)(wn*64 + (lane&7) + ((lane&16)?8:0));
    const uint32_t bOff = (bRow*SROW + ((lane&8)?8:0))*2;
    const uint32_t aBh = smaddr(Ah)+aOff, aBl = smaddr(Al)+aOff;
    const uint32_t bBh = smaddr(Bh)+bOff, bBl = smaddr(Bl)+bOff;

#pragma unroll
    for (int c=0;c<4;c++){ cpa16(sFa + c*16, aG + c*4); cpa16(sFb + c*16, bG + c*4); }
    asm volatile("cp.async.commit_group;\n" ::: "memory");
    asm volatile("cp.async.wait_group 0;\n" ::: "memory");
    __syncthreads();

    for (int k0=0; k0<K; k0+=32){
        {
            float fb_[16];
            *(float4*)&fb_[0]  = *(const float4*)(fAr+0);
            *(float4*)&fb_[4]  = *(const float4*)(fAr+4);
            *(float4*)&fb_[8]  = *(const float4*)(fAr+8);
            *(float4*)&fb_[12] = *(const float4*)(fAr+12);
            cvt16(fb_, ahS, alS);
            *(float4*)&fb_[0]  = *(const float4*)(fBr+0);
            *(float4*)&fb_[4]  = *(const float4*)(fBr+4);
            *(float4*)&fb_[8]  = *(const float4*)(fBr+8);
            *(float4*)&fb_[12] = *(const float4*)(fBr+12);
            cvt16(fb_, bhS, blS);
        }
        __syncthreads();
        if (k0+32 < K){
#pragma unroll
            for (int c=0;c<4;c++){
                cpa16(sFa + c*16, aG + k0 + 32 + c*4);
                cpa16(sFb + c*16, bG + k0 + 32 + c*4);
            }
            asm volatile("cp.async.commit_group;\n" ::: "memory");
        }
#pragma unroll
        for (int kk=0; kk<32; kk+=16){
            uint32_t ah[2][4], al[2][4];
#pragma unroll
            for (int mt=0; mt<2; mt++){
                ldsm4(ah[mt], aBh + (mt*16*SROW + kk)*2);
                ldsm4(al[mt], aBl + (mt*16*SROW + kk)*2);
            }
#pragma unroll
            for (int ntp=0; ntp<4; ntp++){
                uint32_t bh[4], bl[4];
                ldsm4(bh, bBh + (ntp*16*SROW + kk)*2);
                ldsm4(bl, bBl + (ntp*16*SROW + kk)*2);
#pragma unroll
                for (int mt=0; mt<2; mt++){
                    float* c0 = acc[mt][ntp*2+0];
                    float* c1 = acc[mt][ntp*2+1];
                    mma16816(c0, ah[mt], bh+0);
                    mma16816(c0, ah[mt], bl+0);
                    mma16816(c0, al[mt], bh+0);
                    mma16816(c1, ah[mt], bh+2);
                    mma16816(c1, ah[mt], bl+2);
                    mma16816(c1, al[mt], bh+2);
                }
            }
        }
        asm volatile("cp.async.wait_group 0;\n" ::: "memory");
        __syncthreads();
    }

    const int mr = lane>>2, nc = (lane&3)*2;
#pragma unroll
    for (int mt=0; mt<2; mt++){
#pragma unroll
        for (int nt=0; nt<8; nt++){
            int n = bn + wn*64 + nt*8 + nc;
            float b0 = bias[n], b1 = bias[n+1];
            const float* ac = acc[mt][nt];
#pragma unroll
            for (int rr=0; rr<2; rr++){
                int m = bm + wm*32 + mt*16 + mr + rr*8;
                if (m < M){
                    size_t crow = permute ? (size_t)((m&31)*63 + (m>>5)) : (size_t)m;
                    float* cp = C + crow*(size_t)N + n;
                    cp[0] = ac[rr*2+0] + b0;
                    cp[1] = ac[rr*2+1] + b1;
                }
            }
        }
    }
}

// ---------- persistent encoder layer ----------
__global__ __launch_bounds__(256) void enc_layer(
    const float* __restrict__ xgT, const float* __restrict__ Whh,
    const int* __restrict__ lens,
    float* __restrict__ h, float* __restrict__ c,
    float* __restrict__ outp)
{
    extern __shared__ float sm[];
    float* ws = sm;
    float* xs = sm + 16384;

    const int dir = blockIdx.x >> 6, bb = blockIdx.x & 63;
    const int tid = threadIdx.x, w = tid>>5, lane = tid&31;
    const int h_idx = bb*8 + w;

    const float* wbase = Whh + (size_t)dir*Gq*HEq;
#pragma unroll
    for (int g=0; g<4; g++){
        const float4* srcp = (const float4*)(wbase + (size_t)(g*HEq + h_idx)*HEq);
        float4* dst = (float4*)(ws + (w*4+g)*HEq);
        for (int i=lane; i<128; i+=32) dst[i] = srcp[i];
    }
    __syncthreads();

    unsigned base = 0;
    if (tid == 0) base = ld_acq(&g_gen[dir]);

    const int len = lens[lane];
    float* hD = h + (size_t)dir*2*BH;
    float* cD = c + (size_t)dir*2*BH;
    const float* w0 = ws + (w*4+0)*HEq;
    const float* w1 = ws + (w*4+1)*HEq;
    const float* w2 = ws + (w*4+2)*HEq;
    const float* w3 = ws + (w*4+3)*HEq;

    for (int s=0; s<Sq; s++){
        const int pp = s&1, po = pp^1;
        const float4* hs = (const float4*)(hD + pp*BH);
        for (int i=tid; i<4096; i+=256) ((float4*)xs)[i] = __ldcg(hs+i);
        __syncthreads();

        float a0=0.f,a1=0.f,a2=0.f,a3=0.f;
#pragma unroll 4
        for (int k=0;k<HEq;k+=4){
            float4 v0=*(const float4*)(w0+k), v1=*(const float4*)(w1+k);
            float4 v2=*(const float4*)(w2+k), v3=*(const float4*)(w3+k);
            float x0=xs[(k+0)*32+lane], x1=xs[(k+1)*32+lane];
            float x2=xs[(k+2)*32+lane], x3=xs[(k+3)*32+lane];
            a0 += v0.x*x0+v0.y*x1+v0.z*x2+v0.w*x3;
            a1 += v1.x*x0+v1.y*x1+v1.z*x2+v1.w*x3;
            a2 += v2.x*x0+v2.y*x1+v2.z*x2+v2.w*x3;
            a3 += v3.x*x0+v3.y*x1+v3.z*x2+v3.w*x3;
        }
        const int t = dir ? (Sq-1-s) : s;
        const float* xr = xgT + (((size_t)dir*Sq + t)*Gq)*32;
        float gi = a0 + xr[(0*HEq+h_idx)*32 + lane];
        float gf = a1 + xr[(1*HEq+h_idx)*32 + lane];
        float gg = a2 + xr[(2*HEq+h_idx)*32 + lane];
        float go = a3 + xr[(3*HEq+h_idx)*32 + lane];
        float co = __ldcg(&cD[pp*BH + h_idx*32 + lane]);
        float c2 = sigf(gf)*co + sigf(gi)*tanhf(gg);
        float h2 = sigf(go)*tanhf(c2);
        bool valid = t < len;
        float hp = xs[h_idx*32+lane];
        __stcg(&hD[po*BH + h_idx*32 + lane], valid ? h2 : hp);
        __stcg(&cD[po*BH + h_idx*32 + lane], valid ? c2 : co);
        outp[((size_t)lane*Sq + t)*EDq + dir*HEq + h_idx] = valid ? h2 : 0.f;
        gbar(dir, 64, base, s+1);
    }
}

// bridge
__global__ __launch_bounds__(256) void k_bridge(
    const float* __restrict__ hW, const float* __restrict__ hb,
    const float* __restrict__ cW, const float* __restrict__ cb,
    const float* __restrict__ ehT, const float* __restrict__ ecT,
    float* __restrict__ dh, float* __restrict__ dc)
{
    const int b = blockIdx.x, l = blockIdx.y, tid = threadIdx.x;
    __shared__ float hh[EDq], cc[EDq];
    for (int i=tid;i<HEq;i+=256){
        hh[i]     = ehT[(size_t)(l*4+0)*BH + i*32 + b];
        hh[HEq+i] = ehT[(size_t)(l*4+2)*BH + i*32 + b];
        cc[i]     = ecT[(size_t)(l*4+0)*BH + i*32 + b];
        cc[HEq+i] = ecT[(size_t)(l*4+2)*BH + i*32 + b];
    }
    __syncthreads();
    const int w = tid>>5, lane = tid&31;
    for (int j=w;j<HEq;j+=8){
        const float* rh = hW + (size_t)j*EDq;
        const float* rc = cW + (size_t)j*EDq;
        float ah=0.f, ac=0.f;
        for (int k=lane;k<EDq;k+=32){ ah += rh[k]*hh[k]; ac += rc[k]*cc[k]; }
        ah = wsum(ah); ac = wsum(ac);
        if (lane==0){
            float hv = tanhf(ah + hb[j]);
            float cv = tanhf(ac + cb[j]);
            if (l==0){ dh[j*32+b]=hv; dc[j*32+b]=cv; }
            else {
#pragma unroll
                for (int q=1;q<4;q++){ dh[(size_t)q*BH + j*32 + b]=hv; dc[(size_t)q*BH + j*32 + b]=cv; }
            }
        }
    }
}

// ---------- persistent decoder: 128 blocks + prefetch in barrier gaps (R10) ----------
#define DEC_SMEM 168832
#define DNB 128u

__device__ __forceinline__ void stage2(uint4* dst, const unsigned* hsrc,
                                       const unsigned* lsrc, int tid){
    const uint4* h4 = (const uint4*)hsrc;
    const uint4* l4 = (const uint4*)lsrc;
    for (int i=tid; i<2048; i+=512){
        dst[i]      = __ldcg(h4+i);
        dst[2048+i] = __ldcg(l4+i);
    }
}

__global__ __launch_bounds__(512) void dec_all(
    const float* __restrict__ egT, const int* __restrict__ src,
    const float* __restrict__ enc, const float* __restrict__ encA,
    const float* __restrict__ db,
    const float* __restrict__ bh_, const float* __restrict__ bc_,
    float* __restrict__ feat)
{
    extern __shared__ char smc[];
    unsigned* sx  = (unsigned*)smc;
    uint4*    sx4 = (uint4*)smc;
    float* red    = (float*)(smc + 131072);
    float* gg     = (float*)(smc + 163840);
    float* hbuf   = (float*)(smc + 165888);
    float* ssc    = (float*)(smc + 166400);
    float* sh3    = (float*)(smc + 166784);

    const int tid = threadIdx.x, w = tid>>5, lane = tid&31;
    const int bk = blockIdx.x;
    const int nb_ = lane>>2;
    const int wofs[4] = {0, 3145728, 5242880, 7340032};

    unsigned base = 0;
    if (tid == 0) base = ld_acq(&g_gen[2]);
    unsigned bi = 0;

    float c_reg[4];
    if (tid < 128){
        int hl = tid>>5, b = tid&31, h = bk*4+hl;
#pragma unroll
        for (int l=0;l<4;l++) c_reg[l] = __ldcg(&bc_[(size_t)l*BH + h*32 + b]);
    }
    for (int l=0;l<4;l++){
        if (tid < 128){
            int hl = tid>>5, b = tid&31, h = bk*4+hl;
            float hv = __ldcg(&bh_[(size_t)l*BH + h*32 + b]);
            hbuf[tid] = hv;
            if (l==3) __stcg(&g_dh3[h*32 + b], hv);
        }
        __syncthreads();
        if (tid < 64){
            int p = tid>>5, b = tid&31;
            float f0 = hbuf[(2*p)*32+b], f1 = hbuf[(2*p+1)*32+b];
            __nv_bfloat16 h0=__float2bfloat16_rn(f0), h1=__float2bfloat16_rn(f1);
            float r0 = f0-__bfloat162float(h0), r1 = f1-__bfloat162float(h1);
            unsigned hi = (unsigned)__bfloat16_as_ushort(h0) | ((unsigned)__bfloat16_as_ushort(h1)<<16);
            unsigned lo = (unsigned)__bfloat16_as_ushort(__float2bfloat16_rn(r0))
                        | ((unsigned)__bfloat16_as_ushort(__float2bfloat16_rn(r1))<<16);
            int j = bk*2 + p;
            __stcg(&g_hx[((0*4+l)*2+0)*8192 + j*32 + b], hi);
            __stcg(&g_hx[((0*4+l)*2+1)*8192 + j*32 + b], lo);
        }
        __syncthreads();
    }
    gbar(2, DNB, base, ++bi);

    // prologue: region A <- h0(pp0)
    stage2(sx4, g_hx + 0*8192, g_hx + 1*8192, tid);
    __syncthreads();

    for (int t=0; t<TD; t++){
        const int pi = t&1, po = pi^1;

        // ===== phase A: layer0 h-chunk partials (region A pre-staged) =====
        float acc[4][4];
#pragma unroll
        for (int nt=0;nt<4;nt++)
#pragma unroll
            for (int ci=0;ci<4;ci++) acc[nt][ci]=0.f;

        const unsigned* wb0 = g_wf + (size_t)bk*96*256 + lane*4;
#pragma unroll
        for (int kk=0;kk<2;kk++){
            int ks  = 64 + w*2 + kk;
            int ksl = w*2 + kk;
            const unsigned* ap = wb0 + (size_t)ks*256;
            unsigned ah[4], al[4];
            *(uint4*)ah = *(const uint4*)ap;
            *(uint4*)al = *(const uint4*)(ap+128);
            int j0 = ksl*8 + (lane&3);
#pragma unroll
            for (int nt=0;nt<4;nt++){
                int n = nt*8 + nb_;
                unsigned bhf[2] = { sx[j0*32+n], sx[(j0+4)*32+n] };
                unsigned blf[2] = { sx[8192+j0*32+n], sx[8192+(j0+4)*32+n] };
                mma16816(acc[nt], ah, bhf);
                mma16816(acc[nt], ah, blf);
                mma16816(acc[nt], al, bhf);
            }
        }

        // ===== phase B: attention (blocks 0..31) =====
        if (bk < 32){
            const int b = bk;
            if (t==0) sh3[tid] = __ldcg(&g_dh3[tid*32 + b]);
            else      sh3[tid] = __ldcg(&feat[((size_t)(t-1)*32+b)*PKq + tid]);
            __syncthreads();
            const float4* s4 = (const float4*)sh3;
            for (int s=w;s<Sq;s+=16){
                const float4* er = (const float4*)(encA + (size_t)(b*Sq+s)*HEq);
                float v=0.f;
                for (int k4=lane;k4<128;k4+=32){
                    float4 q = er[k4]; float4 hq = s4[k4];
                    v += q.x*hq.x + q.y*hq.y + q.z*hq.z + q.w*hq.w;
                }
                v = wsum(v);
                if (lane==0) ssc[s] = (src[b*Sq+s]==0) ? -1e30f : v;
            }
            __syncthreads();
            if (w==0){
                float m=-1e30f;
                for (int i=lane;i<Sq;i+=32) m = fmaxf(m, ssc[i]);
                m = wmax(m);
                float sum=0.f;
                for (int i=lane;i<Sq;i+=32){ float e=__expf(ssc[i]-m); ssc[i]=e; sum+=e; }
                sum = wsum(sum);
                float inv = 1.f/sum;
                for (int i=lane;i<Sq;i+=32) ssc[i] *= inv;
            }
            __syncthreads();
            {
                int e0 = tid*2;
                float a0=0.f, a1=0.f;
                const float* er = enc + (size_t)b*Sq*EDq + e0;
#pragma unroll 4
                for (int s=0;s<Sq;s++){ float ww = ssc[s]; a0 += ww*er[(size_t)s*EDq]; a1 += ww*er[(size_t)s*EDq+1]; }
                float* fp = feat + ((size_t)t*32+b)*PKq + HEq + e0;
                fp[0]=a0; fp[1]=a1;
                __nv_bfloat16 h0=__float2bfloat16_rn(a0), h1=__float2bfloat16_rn(a1);
                float r0 = a0-__bfloat162float(h0), r1 = a1-__bfloat162float(h1);
                unsigned hi = (unsigned)__bfloat16_as_ushort(h0) | ((unsigned)__bfloat16_as_ushort(h1)<<16);
                unsigned lo = (unsigned)__bfloat16_as_ushort(__float2bfloat16_rn(r0))
                            | ((unsigned)__bfloat16_as_ushort(__float2bfloat16_rn(r1))<<16);
                __stcg(&g_cx[0*16384 + tid*32 + b], hi);
                __stcg(&g_cx[1*16384 + tid*32 + b], lo);
            }
        }
        gbar(2, DNB, base, ++bi);

        // ===== phase C: layer0 ctx chunks =====
        stage2(sx4,      g_cx,        g_cx+16384, tid);
        stage2(sx4+4096, g_cx+8192,   g_cx+24576, tid);
        __syncthreads();
#pragma unroll
        for (int kk=0;kk<4;kk++){
            int ks  = w*4 + kk;
            int v_  = ks>>5, ksl = ks&31;
            const unsigned* ap = wb0 + (size_t)ks*256;
            unsigned ah[4], al[4];
            *(uint4*)ah = *(const uint4*)ap;
            *(uint4*)al = *(const uint4*)(ap+128);
            const unsigned* bh_p = sx + v_*16384;
            const unsigned* bl_p = bh_p + 8192;
            int j0 = ksl*8 + (lane&3);
#pragma unroll
            for (int nt=0;nt<4;nt++){
                int n = nt*8 + nb_;
                unsigned bhf[2] = { bh_p[j0*32+n], bh_p[(j0+4)*32+n] };
                unsigned blf[2] = { bl_p[j0*32+n], bl_p[(j0+4)*32+n] };
                mma16816(acc[nt], ah, bhf);
                mma16816(acc[nt], ah, blf);
                mma16816(acc[nt], al, bhf);
            }
        }
        __syncthreads();
#pragma unroll
        for (int nt=0;nt<4;nt++)
#pragma unroll
            for (int ci=0;ci<4;ci++)
                red[w*512 + (nt*4+ci)*32 + lane] = acc[nt][ci];
        __syncthreads();
        {
            float v=0.f;
#pragma unroll
            for (int w2=0;w2<16;w2++) v += red[w2*512 + tid];
            int q = tid>>5, ln = tid&31;
            int nt = q>>2, ci = q&3;
            int r = (ln>>2) + 8*(ci>>1);
            int n = nt*8 + (ln&3)*2 + (ci&1);
            gg[r*32+n] = v;
        }
        __syncthreads();
        if (tid < 128){
            int hl = tid>>5, b = tid&31, h = bk*4+hl;
            float gi = gg[(hl*4+0)*32+b], gf = gg[(hl*4+1)*32+b];
            float gc = gg[(hl*4+2)*32+b], go = gg[(hl*4+3)*32+b];
            const float* gp = egT + ((size_t)t*Gq)*32;
            gi += gp[(0*HEq+h)*32+b]; gf += gp[(1*HEq+h)*32+b];
            gc += gp[(2*HEq+h)*32+b]; go += gp[(3*HEq+h)*32+b];
            float c2 = sigf(gf)*c_reg[0] + sigf(gi)*tanhf(gc);
            float h2 = sigf(go)*tanhf(c2);
            c_reg[0] = c2;
            hbuf[tid] = h2;
        }
        __syncthreads();
        if (tid < 64){
            int p = tid>>5, b = tid&31;
            float f0 = hbuf[(2*p)*32+b], f1 = hbuf[(2*p+1)*32+b];
            __nv_bfloat16 h0=__float2bfloat16_rn(f0), h1=__float2bfloat16_rn(f1);
            float r0 = f0-__bfloat162float(h0), r1 = f1-__bfloat162float(h1);
            unsigned hi = (unsigned)__bfloat16_as_ushort(h0) | ((unsigned)__bfloat16_as_ushort(h1)<<16);
            unsigned lo = (unsigned)__bfloat16_as_ushort(__float2bfloat16_rn(r0))
                        | ((unsigned)__bfloat16_as_ushort(__float2bfloat16_rn(r1))<<16);
            int j = bk*2 + p;
            __stcg(&g_hx[((po*4+0)*2+0)*8192 + j*32 + b], hi);
            __stcg(&g_hx[((po*4+0)*2+1)*8192 + j*32 + b], lo);
        }
        gbar_arrive(2, DNB);
        stage2(sx4+4096, g_hx+((pi*4+1)*2+0)*8192, g_hx+((pi*4+1)*2+1)*8192, tid);
        gbar_wait(2, base, ++bi);

        // ===== layers 1..3 =====
        for (int l=1; l<4; l++){
            stage2(sx4, g_hx+((po*4+(l-1))*2+0)*8192, g_hx+((po*4+(l-1))*2+1)*8192, tid);
            __syncthreads();
#pragma unroll
            for (int nt=0;nt<4;nt++)
#pragma unroll
                for (int ci=0;ci<4;ci++) acc[nt][ci]=0.f;

            const unsigned* wb = g_wf + wofs[l] + (size_t)bk*64*256 + lane*4;
#pragma unroll
            for (int kk=0;kk<4;kk++){
                int ks  = w*4 + kk;
                int v_  = ks>>5, ksl = ks&31;
                const unsigned* ap = wb + (size_t)ks*256;
                unsigned ah[4], al[4];
                *(uint4*)ah = *(const uint4*)ap;
                *(uint4*)al = *(const uint4*)(ap+128);
                const unsigned* bh_p = sx + v_*16384;
                const unsigned* bl_p = bh_p + 8192;
                int j0 = ksl*8 + (lane&3);
#pragma unroll
                for (int nt=0;nt<4;nt++){
                    int n = nt*8 + nb_;
                    unsigned bhf[2] = { bh_p[j0*32+n], bh_p[(j0+4)*32+n] };
                    unsigned blf[2] = { bl_p[j0*32+n], bl_p[(j0+4)*32+n] };
                    mma16816(acc[nt], ah, bhf);
                    mma16816(acc[nt], ah, blf);
                    mma16816(acc[nt], al, bhf);
                }
            }
            __syncthreads();
#pragma unroll
            for (int nt=0;nt<4;nt++)
#pragma unroll
                for (int ci=0;ci<4;ci++)
                    red[w*512 + (nt*4+ci)*32 + lane] = acc[nt][ci];
            __syncthreads();
            {
                float v=0.f;
#pragma unroll
                for (int w2=0;w2<16;w2++) v += red[w2*512 + tid];
                int q = tid>>5, ln = tid&31;
                int nt = q>>2, ci = q&3;
                int r = (ln>>2) + 8*(ci>>1);
                int n = nt*8 + (ln&3)*2 + (ci&1);
                gg[r*32+n] = v;
            }
            __syncthreads();
            if (tid < 128){
                int hl = tid>>5, b = tid&31, h = bk*4+hl;
                float gi = gg[(hl*4+0)*32+b], gf = gg[(hl*4+1)*32+b];
                float gc = gg[(hl*4+2)*32+b], go = gg[(hl*4+3)*32+b];
                const float* bp = db + (size_t)(l-1)*Gq;
                gi += bp[h]; gf += bp[HEq+h]; gc += bp[2*HEq+h]; go += bp[3*HEq+h];
                float c2 = sigf(gf)*c_reg[l] + sigf(gi)*tanhf(gc);
                float h2 = sigf(go)*tanhf(c2);
                c_reg[l] = c2;
                hbuf[tid] = h2;
                if (l==3) feat[((size_t)t*32+b)*PKq + h] = h2;
            }
            __syncthreads();
            if (tid < 64){
                int p = tid>>5, b = tid&31;
                float f0 = hbuf[(2*p)*32+b], f1 = hbuf[(2*p+1)*32+b];
                __nv_bfloat16 h0=__float2bfloat16_rn(f0), h1=__float2bfloat16_rn(f1);
                float r0 = f0-__bfloat162float(h0), r1 = f1-__bfloat162float(h1);
                unsigned hi = (unsigned)__bfloat16_as_ushort(h0) | ((unsigned)__bfloat16_as_ushort(h1)<<16);
                unsigned lo = (unsigned)__bfloat16_as_ushort(__float2bfloat16_rn(r0))
                            | ((unsigned)__bfloat16_as_ushort(__float2bfloat16_rn(r1))<<16);
                int j = bk*2 + p;
                __stcg(&g_hx[((po*4+l)*2+0)*8192 + j*32 + b], hi);
                __stcg(&g_hx[((po*4+l)*2+1)*8192 + j*32 + b], lo);
            }
            gbar_arrive(2, DNB);
            if (l < 3)
                stage2(sx4+4096, g_hx+((pi*4+l+1)*2+0)*8192, g_hx+((pi*4+l+1)*2+1)*8192, tid);
            else
                stage2(sx4,      g_hx+((po*4+0)*2+0)*8192, g_hx+((po*4+0)*2+1)*8192, tid);
            gbar_wait(2, base, ++bi);
        }
    }
}

static float* sym(const void* s){
    void* p = 0;
    cudaGetSymbolAddress(&p, s);
    return (float*)p;
}

extern "C" void kernel_launch(void* const* d_in, const int* in_sizes, int n_in,
                              void* d_out, int out_size)
{
    const int*   src     = (const int*)  d_in[0];
    const int*   lens    = (const int*)  d_in[1];
    const int*   tgt     = (const int*)  d_in[2];
    const float* enc_emb = (const float*)d_in[3];
    const float* eWih0   = (const float*)d_in[4];
    const float* eWhh0   = (const float*)d_in[5];
    const float* eb0     = (const float*)d_in[6];
    const float* eWih1   = (const float*)d_in[7];
    const float* eWhh1   = (const float*)d_in[8];
    const float* eb1     = (const float*)d_in[9];
    const float* brhW    = (const float*)d_in[10];
    const float* brhb    = (const float*)d_in[11];
    const float* brcW    = (const float*)d_in[12];
    const float* brcb    = (const float*)d_in[13];
    const float* dec_emb = (const float*)d_in[14];
    const float* dWih0   = (const float*)d_in[15];
    const float* dWhh0   = (const float*)d_in[16];
    const float* db0     = (const float*)d_in[17];
    const float* dWih    = (const float*)d_in[18];
    const float* dWhh    = (const float*)d_in[19];
    const float* db      = (const float*)d_in[20];
    const float* attn_W  = (const float*)d_in[21];
    const float* proj_W  = (const float*)d_in[22];
    const float* proj_b  = (const float*)d_in[23];
    float* out = (float*)d_out;

    float *emb = sym(g_emb), *xg = sym(g_xg), *xgT = sym(g_xgT);
    float *x1 = sym(g_x1), *enc = sym(g_enc), *encA = sym(g_encA);
    float *aWT = sym(g_aWT), *bzero = sym(g_bzero);
    float *eh  = sym(g_eh),  *ec = sym(g_ec), *dh = sym(g_dh), *dc = sym(g_dc);
    float *embd= sym(g_embd),*eg = sym(g_eg), *egT = sym(g_egT), *feat = sym(g_feat);
    unsigned *wf = (unsigned*)sym(g_wf);

    cudaFuncSetAttribute(enc_layer,   cudaFuncAttributeMaxDynamicSharedMemorySize, 131072);
    cudaFuncSetAttribute(dec_all,     cudaFuncAttributeMaxDynamicSharedMemorySize, DEC_SMEM);
    cudaFuncSetAttribute(hgemm_split, cudaFuncAttributeMaxDynamicSharedMemorySize, HG_SMEM);

    // decoder weight fragments + attn_W transpose (independent of encoder)
    k_wf<<<4608, 256>>>(dWih0, dWhh0, dWih, dWhh, wf);
    k_aT<<<dim3(16,32), 256>>>(attn_W, aWT);

    // encoder
    k_embed_src<<<Bq*Sq, 256>>>(src, enc_emb, emb);
    k_zero<<<512, 256>>>(eh, ec, 8*BH);
    for (int d=0; d<2; d++)
        hgemm_split<<<dim3(16,24),256,HG_SMEM>>>(emb,Eq, eWih0+(size_t)d*Gq*Eq,Eq, eb0+d*Gq,
                                         xg+(size_t)d*XGS, Bq*Sq, Gq, Eq, 0);
    k_xT<<<2*Sq*64, 256>>>(xg, xgT);
    enc_layer<<<128,256,131072>>>(xgT, eWhh0, lens, eh, ec, x1);
    for (int d=0; d<2; d++)
        hgemm_split<<<dim3(16,24),256,HG_SMEM>>>(x1,EDq, eWih1+(size_t)d*Gq*EDq,EDq, eb1+d*Gq,
                                         xg+(size_t)d*XGS, Bq*Sq, Gq, EDq, 0);
    k_xT<<<2*Sq*64, 256>>>(xg, xgT);
    enc_layer<<<128,256,131072>>>(xgT, eWhh1, lens, eh+4*BH, ec+4*BH, enc);

    // encA = enc @ attn_W^T
    hgemm_split<<<dim3(4,24),256,HG_SMEM>>>(enc,EDq, aWT,EDq, bzero, encA, Bq*Sq, HEq, EDq, 0);

    // bridge + decoder precompute
    k_bridge<<<dim3(32,2),256>>>(brhW, brhb, brcW, brcb, eh, ec, dh, dc);
    k_embed_tgt<<<TD*Bq, 256>>>(tgt, dec_emb, embd);
    hgemm_split<<<dim3(16,16),256,HG_SMEM>>>(embd,Eq, dWih0,Eq+EDq, db0, eg, TD*Bq, Gq, Eq, 0);
    k_egT<<<TD*64, 256>>>(eg, egT);

    // full decoder (persistent, 128 blocks, R10 barrier discipline)
    dec_all<<<128,512,DEC_SMEM>>>(egT, src, enc, encA, db, dh, dc, feat);

    // projection
    hgemm_split<<<dim3(125,16),256,HG_SMEM>>>(feat,PKq, proj_W,PKq, proj_b, out,
                                      TD*Bq, VTq, PKq, 1);
    (void)in_sizes; (void)n_in; (void)out_size;
}